// round 8
// baseline (speedup 1.0000x reference)
#include <cuda_runtime.h>
#include <math.h>
#include <float.h>

#define NB 2
#define NS 1024
#define ND 512
#define NTOK (NB*NS)
#define NNEUR 4096
#define NCAND 288
#define MPC 32
#define GRID_C 16
#define NCELL (GRID_C*GRID_C)
#define NHEAD 8
#define DHEAD 64

// ---------------- device scratch (static, no allocation) ----------------
__device__ float g_Q[NTOK*ND];
__device__ float g_K[NTOK*ND];
__device__ float g_V[NTOK*ND];
__device__ float g_AO[NTOK*ND];
__device__ float g_posbuf[NTOK*2];
__device__ float g_act[2][NTOK*NCAND];
__device__ int   g_off[2][NCELL+1];
__device__ int   g_list[2][NTOK];

// ---------------- helpers ----------------
__device__ __forceinline__ unsigned f2u(float f){
    unsigned u = __float_as_uint(f);
    return (u & 0x80000000u) ? ~u : (u | 0x80000000u);
}
__device__ __forceinline__ float u2f(unsigned u){
    u = (u & 0x80000000u) ? (u & 0x7FFFFFFFu) : ~u;
    return __uint_as_float(u);
}
__device__ __forceinline__ float egf(float score, float tau){
    float raw = score - tau;
    float gate = raw > 0.f ? raw : 1e-8f * expf(raw);
    return expf(gate) - 1.0f;
}
__device__ __forceinline__ int cell_of(float p, float pm, float pr){
    int c = (int)(((p - pm) / pr) * GRID_C);
    return min(max(c, 0), GRID_C - 1);
}

// ================= fused binning: one block, one launch =================
__global__ __launch_bounds__(1024)
void bin_all(const float* __restrict__ qk_pos, const float* __restrict__ v_pos,
             const float* __restrict__ pos_min, const float* __restrict__ pos_range){
    __shared__ int cnt[2*NCELL];
    int tid = threadIdx.x;
    for (int i = tid; i < 2*NCELL; i += 1024) cnt[i] = 0;
    __syncthreads();
    float pm0 = pos_min[0], pm1 = pos_min[1], pr0 = pos_range[0], pr1 = pos_range[1];
    int c0[2], c1[2];
    #pragma unroll
    for (int r = 0; r < 2; r++){
        int t = tid + r * 1024;
        c0[r] = cell_of(qk_pos[t*2], pm0, pr0) * GRID_C + cell_of(qk_pos[t*2+1], pm1, pr1);
        c1[r] = cell_of(v_pos[t*2],  pm0, pr0) * GRID_C + cell_of(v_pos[t*2+1],  pm1, pr1);
        atomicAdd(&cnt[c0[r]], 1);
        atomicAdd(&cnt[NCELL + c1[r]], 1);
    }
    __syncthreads();
    if (tid < 2){
        int acc = 0;
        for (int c = 0; c < NCELL; c++){ g_off[tid][c] = acc; acc += cnt[tid*NCELL + c]; }
        g_off[tid][NCELL] = acc;
    }
    __syncthreads();
    for (int i = tid; i < 2*NCELL; i += 1024) cnt[i] = 0;
    __syncthreads();
    #pragma unroll
    for (int r = 0; r < 2; r++){
        int t = tid + r * 1024;
        int p0 = atomicAdd(&cnt[c0[r]], 1);
        g_list[0][g_off[0][c0[r]] + p0] = t;
        int p1 = atomicAdd(&cnt[NCELL + c1[r]], 1);
        g_list[1][g_off[1][c1[r]] + p1] = t;
    }
}

// ================= cell-binned candidate scoring: 8 tokens per pass =================
__global__ __launch_bounds__(256)
void score_kernel(const float* __restrict__ x,
                  const float* __restrict__ qk_neurons, const float* __restrict__ v_neurons,
                  const int* __restrict__ cm_qk, const int* __restrict__ cm_v){
    int set  = blockIdx.y;
    int cell = blockIdx.x;
    const float* neur = set ? v_neurons : qk_neurons;
    const int*   cmap = set ? cm_v : cm_qk;
    __shared__ float xs[8][ND];
    __shared__ int cand[NCAND];
    __shared__ int toks[8];
    int tid = threadIdx.x;
    int start = g_off[set][cell], end = g_off[set][cell+1];
    if (start >= end) return;
    for (int i = tid; i < NCAND; i += 256){
        int cx = cell >> 4, cy = cell & 15;
        int c = i / MPC;
        int rx = min(max(cx + c / 3 - 1, 0), GRID_C - 1);
        int ry = min(max(cy + c % 3 - 1, 0), GRID_C - 1);
        int id = cmap[(rx * GRID_C + ry) * MPC + (i & 31)];
        cand[i] = id < 0 ? 0 : id;
    }
    int w = tid >> 5, ln = tid & 31;
    for (int g = start; g < end; g += 8){
        __syncthreads();
        if (tid < 8) toks[tid] = g_list[set][min(g + tid, end - 1)];
        __syncthreads();
        for (int i = tid; i < 8 * (ND/4); i += 256){
            int t = i >> 7, e = i & 127;
            ((float4*)&xs[t][0])[e] = ((const float4*)(x + (size_t)toks[t] * ND))[e];
        }
        __syncthreads();
        float xr[8][16];
        #pragma unroll
        for (int t = 0; t < 8; t++)
            #pragma unroll
            for (int e = 0; e < 16; e++) xr[t][e] = xs[t][e * 32 + ln];
        for (int i = w; i < NCAND; i += 8){
            const float* row = neur + (size_t)cand[i] * ND;
            float a[8];
            #pragma unroll
            for (int t = 0; t < 8; t++) a[t] = 0.f;
            #pragma unroll
            for (int e = 0; e < 16; e++){
                float r = row[e * 32 + ln];
                #pragma unroll
                for (int t = 0; t < 8; t++) a[t] += r * xr[t][e];
            }
            #pragma unroll
            for (int o = 16; o; o >>= 1){
                #pragma unroll
                for (int t = 0; t < 8; t++) a[t] += __shfl_xor_sync(0xffffffffu, a[t], o);
            }
            if (ln == 0){
                #pragma unroll
                for (int t = 0; t < 8; t++)
                    if (g + t < end) g_act[set][(size_t)toks[t] * NCAND + i] = a[t];
            }
        }
    }
}

// ================= per-token gating + weighted gather =================
struct GSmem {
    float actA[NCAND]; float actB[NCAND];
    int   candA[NCAND]; int candB[NCAND];
    float wq[NCAND], wk[NCAND], wv[NCAND];
    int   klA[NCAND], klB[NCAND];
    float thr[4];
    float redf[5][8];
    int   wcntA[8], wcntB[8];
    int   icntA, icntB;
    float sc[3];
};

// single-warp exact 32nd-largest (counting duplicates) via bitwise binary search
__device__ __forceinline__ void warp_kth32(const float* act, const int* cand, float* out2){
    int ln = threadIdx.x & 31;
    unsigned vu[9]; unsigned mxu = 0;
    #pragma unroll
    for (int j = 0; j < 9; j++){
        int idx = ln + j * 32;
        float v = (cand[idx] >= 0) ? act[idx] : -1e9f;
        unsigned u = f2u(v);
        vu[j] = u;
        mxu = max(mxu, u);
    }
    mxu = __reduce_max_sync(0xffffffffu, mxu);
    unsigned T = 0u;
    #pragma unroll
    for (int bit = 31; bit >= 0; bit--){
        unsigned Tc = T | (1u << bit);
        int c = 0;
        #pragma unroll
        for (int j = 0; j < 9; j++) c += (vu[j] >= Tc) ? 1 : 0;
        c = __reduce_add_sync(0xffffffffu, c);
        if (c >= 32) T = Tc;
    }
    if (ln == 0){ out2[0] = u2f(T); out2[1] = u2f(mxu); }
}

__global__ __launch_bounds__(256)
void gate_kernel(const float* __restrict__ qk_pos, const float* __restrict__ v_pos,
                 const float* __restrict__ tau_Q, const float* __restrict__ tau_K,
                 const float* __restrict__ tau_V,
                 const float* __restrict__ qk_neurons, const float* __restrict__ v_neurons,
                 const float* __restrict__ npos_qk, const float* __restrict__ npos_v,
                 const int* __restrict__ cm_qk, const int* __restrict__ cm_v,
                 const float* __restrict__ pos_min, const float* __restrict__ pos_range)
{
    __shared__ GSmem sm;
    int token = blockIdx.x;
    int tid = threadIdx.x;
    int w = tid >> 5, ln = tid & 31;
    float pm0 = pos_min[0], pm1 = pos_min[1];
    float pr0 = pos_range[0], pr1 = pos_range[1];

    float pxA = qk_pos[token*2], pyA = qk_pos[token*2+1];
    float pxB = v_pos[token*2],  pyB = v_pos[token*2+1];
    int cxA = cell_of(pxA, pm0, pr0), cyA = cell_of(pyA, pm1, pr1);
    int cxB = cell_of(pxB, pm0, pr0), cyB = cell_of(pyB, pm1, pr1);

    for (int i = tid; i < NCAND; i += 256){
        int c = i / MPC;
        int rxA = min(max(cxA + c / 3 - 1, 0), GRID_C - 1);
        int ryA = min(max(cyA + c % 3 - 1, 0), GRID_C - 1);
        sm.candA[i] = cm_qk[(rxA * GRID_C + ryA) * MPC + (i & 31)];
        int rxB = min(max(cxB + c / 3 - 1, 0), GRID_C - 1);
        int ryB = min(max(cyB + c % 3 - 1, 0), GRID_C - 1);
        sm.candB[i] = cm_v[(rxB * GRID_C + ryB) * MPC + (i & 31)];
        sm.actA[i] = g_act[0][(size_t)token * NCAND + i];
        sm.actB[i] = g_act[1][(size_t)token * NCAND + i];
    }
    if (tid == 0){ sm.icntA = 0; sm.icntB = 0; }
    __syncthreads();

    if (w == 0)      warp_kth32(sm.actA, sm.candA, &sm.thr[0]);
    else if (w == 1) warp_kth32(sm.actB, sm.candB, &sm.thr[2]);
    __syncthreads();

    float tq = tau_Q[token], tk = tau_K[token], tvt = tau_V[token];
    float akA = sm.thr[0], mxA = sm.thr[1], akB = sm.thr[2], mxB = sm.thr[3];
    float tvQ = egf(akA, tq), tvK = egf(akA, tk), tvV = egf(akB, tvt);
    float stQ = tanhf(egf(mxA, tq)), stK = tanhf(egf(mxA, tk)), stV = tanhf(egf(mxB, tvt));

    float sQ = 0.f, sK = 0.f, sV = 0.f, sQpd = 0.f, sVpd = 0.f;
    for (int r = 0; r < 2; r++){
        int i = r * 256 + tid;
        bool keepA = false, keepB = false;
        float a = 0.f, b = 0.f, wQ = 0.f, wK = 0.f, wV = 0.f;
        int cA = -1, cB = -1;
        if (i < NCAND){
            cA = sm.candA[i];
            a  = sm.actA[i];
            float scA = (cA >= 0) ? a : -1e9f;
            float eQ = egf(scA, tq), eK = egf(scA, tk);
            float kq = (eQ >= tvQ) ? eQ : 0.f;
            float kk = (eK >= tvK) ? eK : 0.f;
            if (cA >= 0){
                wQ = kq; wK = kk;
                sQ += wQ; sK += wK;
                if (wQ > 0.f){
                    float dx = pxA - npos_qk[cA*2], dy = pyA - npos_qk[cA*2+1];
                    sQpd += wQ * (dx*dx + dy*dy);
                }
                keepA = (wQ != 0.f) || (wK != 0.f);
            }
            cB = sm.candB[i];
            b  = sm.actB[i];
            float scB = (cB >= 0) ? b : -1e9f;
            float eV = egf(scB, tvt);
            float kv = (eV >= tvV) ? eV : 0.f;
            if (cB >= 0){
                wV = kv;
                sV += wV;
                if (wV > 0.f){
                    float dx = pxB - npos_v[cB*2], dy = pyB - npos_v[cB*2+1];
                    sVpd += wV * (dx*dx + dy*dy);
                }
                keepB = (wV != 0.f);
            }
        }
        unsigned lt = (1u << ln) - 1u;
        unsigned balA = __ballot_sync(0xffffffffu, keepA);
        unsigned balB = __ballot_sync(0xffffffffu, keepB);
        int pA = __popc(balA & lt), pB = __popc(balB & lt);
        if (ln == 0){ sm.wcntA[w] = __popc(balA); sm.wcntB[w] = __popc(balB); }
        __syncthreads();
        if (tid == 0){
            int bA = sm.icntA, bB = sm.icntB;
            for (int w2 = 0; w2 < 8; w2++){
                int tA = sm.wcntA[w2]; sm.wcntA[w2] = bA; bA += tA;
                int tB = sm.wcntB[w2]; sm.wcntB[w2] = bB; bB += tB;
            }
            sm.icntA = bA; sm.icntB = bB;
        }
        __syncthreads();
        if (keepA){
            int p = sm.wcntA[w] + pA;
            sm.klA[p] = cA; sm.wq[p] = a * wQ; sm.wk[p] = a * wK;
        }
        if (keepB){
            int p = sm.wcntB[w] + pB;
            sm.klB[p] = cB; sm.wv[p] = b * wV;
        }
        __syncthreads();
    }
    #pragma unroll
    for (int o = 16; o; o >>= 1){
        sQ   += __shfl_xor_sync(0xffffffffu, sQ, o);
        sK   += __shfl_xor_sync(0xffffffffu, sK, o);
        sV   += __shfl_xor_sync(0xffffffffu, sV, o);
        sQpd += __shfl_xor_sync(0xffffffffu, sQpd, o);
        sVpd += __shfl_xor_sync(0xffffffffu, sVpd, o);
    }
    if (ln == 0){
        sm.redf[0][w] = sQ; sm.redf[1][w] = sK; sm.redf[2][w] = sV;
        sm.redf[3][w] = sQpd; sm.redf[4][w] = sVpd;
    }
    __syncthreads();
    if (tid == 0){
        float a0=0.f, a1=0.f, a2=0.f, a3=0.f, a4=0.f;
        for (int w2 = 0; w2 < 8; w2++){
            a0 += sm.redf[0][w2]; a1 += sm.redf[1][w2]; a2 += sm.redf[2][w2];
            a3 += sm.redf[3][w2]; a4 += sm.redf[4][w2];
        }
        float scQ = stQ / (a0 + 1e-8f);
        float scK = stK / (a1 + 1e-8f);
        float scV = stV / (a2 + 1e-8f);
        sm.sc[0] = scQ; sm.sc[1] = scK; sm.sc[2] = scV;
        g_posbuf[token] = scQ * a3;
        g_posbuf[NTOK + token] = scV * a4;
    }
    __syncthreads();
    {
        int nkA = sm.icntA;
        float scQ = sm.sc[0], scK = sm.sc[1];
        float2 q = make_float2(0.f, 0.f), k = make_float2(0.f, 0.f);
        #pragma unroll 4
        for (int j = 0; j < nkA; j++){
            const float2* row = (const float2*)(qk_neurons + (size_t)sm.klA[j] * ND);
            float cq = sm.wq[j] * scQ, ck = sm.wk[j] * scK;
            float2 r = row[tid];
            q.x += cq * r.x; q.y += cq * r.y;
            k.x += ck * r.x; k.y += ck * r.y;
        }
        ((float2*)(g_Q + (size_t)token * ND))[tid] = q;
        ((float2*)(g_K + (size_t)token * ND))[tid] = k;
    }
    {
        int nkB = sm.icntB;
        float scV = sm.sc[2];
        float2 v = make_float2(0.f, 0.f);
        #pragma unroll 4
        for (int j = 0; j < nkB; j++){
            const float2* row = (const float2*)(v_neurons + (size_t)sm.klB[j] * ND);
            float cv = sm.wv[j] * scV;
            float2 r = row[tid];
            v.x += cv * r.x; v.y += cv * r.y;
        }
        ((float2*)(g_V + (size_t)token * ND))[tid] = v;
    }
}

// ================= causal flash attention: 32q x 64kv, 128 threads =================
// shared K/V smem buffer + reg cap -> 8 blocks/SM target (occupancy experiment).
__global__ __launch_bounds__(128, 8)
void attn_kernel(){
    __shared__ float QT[64][36];  // [d][q]
    __shared__ float KV[64][68];  // scores: [d][k]; PV: [t][d]
    int tid = threadIdx.x;
    int qt = blockIdx.x & 31;
    int h  = (blockIdx.x >> 5) & 7;
    int b  = blockIdx.x >> 8;
    int q0 = qt * 32;
    const float* Qg = g_Q + (size_t)b * NS * ND + h * DHEAD;
    const float* Kg = g_K + (size_t)b * NS * ND + h * DHEAD;
    const float* Vg = g_V + (size_t)b * NS * ND + h * DHEAD;

    for (int i = tid; i < 32 * 64; i += 128){
        int r = i >> 6, c = i & 63;
        QT[c][r] = Qg[(size_t)(q0 + r) * ND + c];
    }
    int tx = tid & 15, ty = tid >> 4;   // ty 0..7 -> 4 q rows each
    int lane = tid & 31;
    float acc[4][4];
    float m[4], l[4];
    #pragma unroll
    for (int qi = 0; qi < 4; qi++){
        m[qi] = -FLT_MAX; l[qi] = 0.f;
        #pragma unroll
        for (int di = 0; di < 4; di++) acc[qi][di] = 0.f;
    }
    int ntile = qt / 2 + 1;
    for (int kt = 0; kt < ntile; kt++){
        int t0 = kt * 64;
        __syncthreads();
        for (int i = tid; i < 64 * 64; i += 128){
            int r = i >> 6, c = i & 63;
            KV[c][r] = Kg[(size_t)(t0 + r) * ND + c];   // [d][k]
        }
        __syncthreads();
        float sf[4][4];
        #pragma unroll
        for (int qi = 0; qi < 4; qi++)
            #pragma unroll
            for (int ki = 0; ki < 4; ki++) sf[qi][ki] = 0.f;
        #pragma unroll 4
        for (int d = 0; d < 64; d++){
            float4 qv = *(const float4*)&QT[d][ty * 4];
            float4 kv = *(const float4*)&KV[d][tx * 4];
            float qa[4] = {qv.x, qv.y, qv.z, qv.w};
            float ka[4] = {kv.x, kv.y, kv.z, kv.w};
            #pragma unroll
            for (int qi = 0; qi < 4; qi++)
                #pragma unroll
                for (int ki = 0; ki < 4; ki++) sf[qi][ki] += qa[qi] * ka[ki];
        }
        const float scl = 0.125f;
        bool diag = (t0 + 64 > q0);
        // softmax in place: sf becomes p
        #pragma unroll
        for (int qi = 0; qi < 4; qi++){
            int qg = q0 + ty * 4 + qi;
            float rm = -FLT_MAX;
            #pragma unroll
            for (int ki = 0; ki < 4; ki++){
                int tg = t0 + tx * 4 + ki;
                float v = (!diag || tg <= qg) ? sf[qi][ki] * scl : -FLT_MAX;
                sf[qi][ki] = v;
                rm = fmaxf(rm, v);
            }
            #pragma unroll
            for (int o = 1; o < 16; o <<= 1) rm = fmaxf(rm, __shfl_xor_sync(0xffffffffu, rm, o));
            float mn = fmaxf(m[qi], rm);
            float corr = expf(m[qi] - mn);
            float rs = 0.f;
            #pragma unroll
            for (int ki = 0; ki < 4; ki++){
                float e = expf(sf[qi][ki] - mn);
                sf[qi][ki] = e;
                rs += e;
            }
            #pragma unroll
            for (int o = 1; o < 16; o <<= 1) rs += __shfl_xor_sync(0xffffffffu, rs, o);
            l[qi] = l[qi] * corr + rs;
            #pragma unroll
            for (int di = 0; di < 4; di++) acc[qi][di] *= corr;
            m[qi] = mn;
        }
        __syncthreads();
        for (int i = tid; i < 64 * 64; i += 128){
            int r = i >> 6, c = i & 63;
            KV[r][c] = Vg[(size_t)(t0 + r) * ND + c];   // [t][d]
        }
        __syncthreads();
        #pragma unroll 2
        for (int tg = 0; tg < 16; tg++){
            int src = (lane & 16) | tg;
            #pragma unroll
            for (int ki = 0; ki < 4; ki++){
                int t = tg * 4 + ki;
                float4 vv = *(const float4*)&KV[t][tx * 4];
                float pq0 = __shfl_sync(0xffffffffu, sf[0][ki], src);
                float pq1 = __shfl_sync(0xffffffffu, sf[1][ki], src);
                float pq2 = __shfl_sync(0xffffffffu, sf[2][ki], src);
                float pq3 = __shfl_sync(0xffffffffu, sf[3][ki], src);
                acc[0][0] += pq0 * vv.x; acc[0][1] += pq0 * vv.y; acc[0][2] += pq0 * vv.z; acc[0][3] += pq0 * vv.w;
                acc[1][0] += pq1 * vv.x; acc[1][1] += pq1 * vv.y; acc[1][2] += pq1 * vv.z; acc[1][3] += pq1 * vv.w;
                acc[2][0] += pq2 * vv.x; acc[2][1] += pq2 * vv.y; acc[2][2] += pq2 * vv.z; acc[2][3] += pq2 * vv.w;
                acc[3][0] += pq3 * vv.x; acc[3][1] += pq3 * vv.y; acc[3][2] += pq3 * vv.z; acc[3][3] += pq3 * vv.w;
            }
        }
    }
    float* Og = g_AO + (size_t)b * NS * ND + h * DHEAD;
    #pragma unroll
    for (int qi = 0; qi < 4; qi++){
        float inv = 1.0f / l[qi];
        float4 o4;
        o4.x = acc[qi][0] * inv; o4.y = acc[qi][1] * inv;
        o4.z = acc[qi][2] * inv; o4.w = acc[qi][3] * inv;
        *(float4*)&Og[(size_t)(q0 + ty * 4 + qi) * ND + tx * 4] = o4;
    }
}

// final projection: out = g_AO[2048x512] @ expand_O[512x512]; block (0,0) also
// writes the pos_loss tail element.
__global__ __launch_bounds__(256)
void out_gemm(const float* __restrict__ Bmat, float* __restrict__ out, int has_tail){
    __shared__ float As[64][33];
    __shared__ float Bs[32][65];
    int tid = threadIdx.x;
    if (has_tail && blockIdx.x == 0 && blockIdx.y == 0){
        __shared__ float red[8];
        float s = 0.f;
        for (int i = tid; i < NTOK * 2; i += 256) s += g_posbuf[i];
        #pragma unroll
        for (int o = 16; o; o >>= 1) s += __shfl_xor_sync(0xffffffffu, s, o);
        if ((tid & 31) == 0) red[tid >> 5] = s;
        __syncthreads();
        if (tid == 0){
            float t = 0.f;
            for (int w = 0; w < 8; w++) t += red[w];
            out[(size_t)NTOK * ND] = t * (1.0f / (8.0f * 73728.0f));
        }
        __syncthreads();
    }
    int m0 = blockIdx.y * 64, n0 = blockIdx.x * 64;
    int tx = tid & 15, ty = tid >> 4;
    float acc[4][4];
    #pragma unroll
    for (int i = 0; i < 4; i++)
        #pragma unroll
        for (int j = 0; j < 4; j++) acc[i][j] = 0.f;
    for (int k0 = 0; k0 < ND; k0 += 32){
        __syncthreads();
        for (int i = tid; i < 64 * 32; i += 256){
            int r = i >> 5, c = i & 31;
            As[r][c] = g_AO[(size_t)(m0 + r) * ND + k0 + c];
        }
        for (int i = tid; i < 32 * 64; i += 256){
            int r = i >> 6, c = i & 63;
            Bs[r][c] = Bmat[(size_t)(k0 + r) * ND + n0 + c];
        }
        __syncthreads();
        #pragma unroll 8
        for (int k = 0; k < 32; k++){
            float a[4], bv[4];
            #pragma unroll
            for (int qi = 0; qi < 4; qi++) a[qi] = As[ty * 4 + qi][k];
            #pragma unroll
            for (int ni = 0; ni < 4; ni++) bv[ni] = Bs[k][tx * 4 + ni];
            #pragma unroll
            for (int qi = 0; qi < 4; qi++)
                #pragma unroll
                for (int ni = 0; ni < 4; ni++) acc[qi][ni] += a[qi] * bv[ni];
        }
    }
    #pragma unroll
    for (int qi = 0; qi < 4; qi++)
        #pragma unroll
        for (int ni = 0; ni < 4; ni++)
            out[(size_t)(m0 + ty * 4 + qi) * ND + n0 + tx * 4 + ni] = acc[qi][ni];
}

extern "C" void kernel_launch(void* const* d_in, const int* in_sizes, int n_in,
                              void* d_out, int out_size){
    const float* x          = (const float*)d_in[0];
    const float* qk_pos     = (const float*)d_in[1];
    const float* v_pos      = (const float*)d_in[2];
    const float* tau_Q      = (const float*)d_in[3];
    const float* tau_K      = (const float*)d_in[4];
    const float* tau_V      = (const float*)d_in[5];
    const float* qk_neurons = (const float*)d_in[6];
    const float* v_neurons  = (const float*)d_in[7];
    const float* npos_qk    = (const float*)d_in[8];
    const float* npos_v     = (const float*)d_in[9];
    const int*   cm_qk      = (const int*)d_in[10];
    const int*   cm_v       = (const int*)d_in[11];
    const float* pos_min    = (const float*)d_in[12];
    const float* pos_range  = (const float*)d_in[13];
    const float* expand_O   = (const float*)d_in[14];
    float* out = (float*)d_out;

    bin_all<<<1, 1024>>>(qk_pos, v_pos, pos_min, pos_range);
    dim3 sg(NCELL, 2);
    score_kernel<<<sg, 256>>>(x, qk_neurons, v_neurons, cm_qk, cm_v);
    gate_kernel<<<NTOK, 256>>>(qk_pos, v_pos, tau_Q, tau_K, tau_V,
                               qk_neurons, v_neurons, npos_qk, npos_v,
                               cm_qk, cm_v, pos_min, pos_range);
    attn_kernel<<<NB * NHEAD * 32, 128>>>();
    int has_tail = (out_size > NTOK * ND) ? 1 : 0;
    dim3 g(ND / 64, NTOK / 64);
    out_gemm<<<g, 256>>>(expand_O, out, has_tail);
}

// round 9
// speedup vs baseline: 1.2082x; 1.2082x over previous
#include <cuda_runtime.h>
#include <math.h>
#include <float.h>

#define NB 2
#define NS 1024
#define ND 512
#define NTOK (NB*NS)
#define NNEUR 4096
#define NCAND 288
#define MPC 32
#define GRID_C 16
#define NCELL (GRID_C*GRID_C)
#define NHEAD 8
#define DHEAD 64
#define NPB (NB*NHEAD*32)   // 512 partial blocks (b,h,qt)

// ---------------- device scratch (static, no allocation) ----------------
__device__ float g_Q[NTOK*ND];
__device__ float g_K[NTOK*ND];
__device__ float g_V[NTOK*ND];
__device__ float g_AO[NTOK*ND];
__device__ float g_posbuf[NTOK*2];
__device__ float g_act[2][NTOK*NCAND];
__device__ int   g_off[2][NCELL+1];
__device__ int   g_list[2][NTOK];
__device__ float g_pacc[2][NPB][32*64];
__device__ float g_pml[2][NPB][64];

// ---------------- helpers ----------------
__device__ __forceinline__ unsigned f2u(float f){
    unsigned u = __float_as_uint(f);
    return (u & 0x80000000u) ? ~u : (u | 0x80000000u);
}
__device__ __forceinline__ float u2f(unsigned u){
    u = (u & 0x80000000u) ? (u & 0x7FFFFFFFu) : ~u;
    return __uint_as_float(u);
}
__device__ __forceinline__ float egf(float score, float tau){
    float raw = score - tau;
    float gate = raw > 0.f ? raw : 1e-8f * expf(raw);
    return expf(gate) - 1.0f;
}
__device__ __forceinline__ int cell_of(float p, float pm, float pr){
    int c = (int)(((p - pm) / pr) * GRID_C);
    return min(max(c, 0), GRID_C - 1);
}

// ================= fused binning: one block, one launch =================
__global__ __launch_bounds__(1024)
void bin_all(const float* __restrict__ qk_pos, const float* __restrict__ v_pos,
             const float* __restrict__ pos_min, const float* __restrict__ pos_range){
    __shared__ int cnt[2*NCELL];
    int tid = threadIdx.x;
    for (int i = tid; i < 2*NCELL; i += 1024) cnt[i] = 0;
    __syncthreads();
    float pm0 = pos_min[0], pm1 = pos_min[1], pr0 = pos_range[0], pr1 = pos_range[1];
    int c0[2], c1[2];
    #pragma unroll
    for (int r = 0; r < 2; r++){
        int t = tid + r * 1024;
        c0[r] = cell_of(qk_pos[t*2], pm0, pr0) * GRID_C + cell_of(qk_pos[t*2+1], pm1, pr1);
        c1[r] = cell_of(v_pos[t*2],  pm0, pr0) * GRID_C + cell_of(v_pos[t*2+1],  pm1, pr1);
        atomicAdd(&cnt[c0[r]], 1);
        atomicAdd(&cnt[NCELL + c1[r]], 1);
    }
    __syncthreads();
    if (tid < 2){
        int acc = 0;
        for (int c = 0; c < NCELL; c++){ g_off[tid][c] = acc; acc += cnt[tid*NCELL + c]; }
        g_off[tid][NCELL] = acc;
    }
    __syncthreads();
    for (int i = tid; i < 2*NCELL; i += 1024) cnt[i] = 0;
    __syncthreads();
    #pragma unroll
    for (int r = 0; r < 2; r++){
        int t = tid + r * 1024;
        int p0 = atomicAdd(&cnt[c0[r]], 1);
        g_list[0][g_off[0][c0[r]] + p0] = t;
        int p1 = atomicAdd(&cnt[NCELL + c1[r]], 1);
        g_list[1][g_off[1][c1[r]] + p1] = t;
    }
}

// ================= cell-binned candidate scoring: 8 tokens per pass =================
__global__ __launch_bounds__(256)
void score_kernel(const float* __restrict__ x,
                  const float* __restrict__ qk_neurons, const float* __restrict__ v_neurons,
                  const int* __restrict__ cm_qk, const int* __restrict__ cm_v){
    int set  = blockIdx.y;
    int cell = blockIdx.x;
    const float* neur = set ? v_neurons : qk_neurons;
    const int*   cmap = set ? cm_v : cm_qk;
    __shared__ float xs[8][ND];
    __shared__ int cand[NCAND];
    __shared__ int toks[8];
    int tid = threadIdx.x;
    int start = g_off[set][cell], end = g_off[set][cell+1];
    if (start >= end) return;
    for (int i = tid; i < NCAND; i += 256){
        int cx = cell >> 4, cy = cell & 15;
        int c = i / MPC;
        int rx = min(max(cx + c / 3 - 1, 0), GRID_C - 1);
        int ry = min(max(cy + c % 3 - 1, 0), GRID_C - 1);
        int id = cmap[(rx * GRID_C + ry) * MPC + (i & 31)];
        cand[i] = id < 0 ? 0 : id;
    }
    int w = tid >> 5, ln = tid & 31;
    for (int g = start; g < end; g += 8){
        __syncthreads();
        if (tid < 8) toks[tid] = g_list[set][min(g + tid, end - 1)];
        __syncthreads();
        for (int i = tid; i < 8 * (ND/4); i += 256){
            int t = i >> 7, e = i & 127;
            ((float4*)&xs[t][0])[e] = ((const float4*)(x + (size_t)toks[t] * ND))[e];
        }
        __syncthreads();
        float xr[8][16];
        #pragma unroll
        for (int t = 0; t < 8; t++)
            #pragma unroll
            for (int e = 0; e < 16; e++) xr[t][e] = xs[t][e * 32 + ln];
        for (int i = w; i < NCAND; i += 8){
            const float* row = neur + (size_t)cand[i] * ND;
            float a[8];
            #pragma unroll
            for (int t = 0; t < 8; t++) a[t] = 0.f;
            #pragma unroll
            for (int e = 0; e < 16; e++){
                float r = row[e * 32 + ln];
                #pragma unroll
                for (int t = 0; t < 8; t++) a[t] += r * xr[t][e];
            }
            #pragma unroll
            for (int o = 16; o; o >>= 1){
                #pragma unroll
                for (int t = 0; t < 8; t++) a[t] += __shfl_xor_sync(0xffffffffu, a[t], o);
            }
            if (ln == 0){
                #pragma unroll
                for (int t = 0; t < 8; t++)
                    if (g + t < end) g_act[set][(size_t)toks[t] * NCAND + i] = a[t];
            }
        }
    }
}

// ================= per-token gating + weighted gather =================
struct GSmem {
    float actA[NCAND]; float actB[NCAND];
    int   candA[NCAND]; int candB[NCAND];
    float wq[NCAND], wk[NCAND], wv[NCAND];
    int   klA[NCAND], klB[NCAND];
    float thr[4];
    float redf[5][8];
    int   wcntA[8], wcntB[8];
    int   icntA, icntB;
    float sc[3];
};

// single-warp exact 32nd-largest (counting duplicates) via bitwise binary search
__device__ __forceinline__ void warp_kth32(const float* act, const int* cand, float* out2){
    int ln = threadIdx.x & 31;
    unsigned vu[9]; unsigned mxu = 0;
    #pragma unroll
    for (int j = 0; j < 9; j++){
        int idx = ln + j * 32;
        float v = (cand[idx] >= 0) ? act[idx] : -1e9f;
        unsigned u = f2u(v);
        vu[j] = u;
        mxu = max(mxu, u);
    }
    mxu = __reduce_max_sync(0xffffffffu, mxu);
    unsigned T = 0u;
    #pragma unroll
    for (int bit = 31; bit >= 0; bit--){
        unsigned Tc = T | (1u << bit);
        int c = 0;
        #pragma unroll
        for (int j = 0; j < 9; j++) c += (vu[j] >= Tc) ? 1 : 0;
        c = __reduce_add_sync(0xffffffffu, c);
        if (c >= 32) T = Tc;
    }
    if (ln == 0){ out2[0] = u2f(T); out2[1] = u2f(mxu); }
}

__global__ __launch_bounds__(256)
void gate_kernel(const float* __restrict__ qk_pos, const float* __restrict__ v_pos,
                 const float* __restrict__ tau_Q, const float* __restrict__ tau_K,
                 const float* __restrict__ tau_V,
                 const float* __restrict__ qk_neurons, const float* __restrict__ v_neurons,
                 const float* __restrict__ npos_qk, const float* __restrict__ npos_v,
                 const int* __restrict__ cm_qk, const int* __restrict__ cm_v,
                 const float* __restrict__ pos_min, const float* __restrict__ pos_range)
{
    __shared__ GSmem sm;
    int token = blockIdx.x;
    int tid = threadIdx.x;
    int w = tid >> 5, ln = tid & 31;
    float pm0 = pos_min[0], pm1 = pos_min[1];
    float pr0 = pos_range[0], pr1 = pos_range[1];

    float pxA = qk_pos[token*2], pyA = qk_pos[token*2+1];
    float pxB = v_pos[token*2],  pyB = v_pos[token*2+1];
    int cxA = cell_of(pxA, pm0, pr0), cyA = cell_of(pyA, pm1, pr1);
    int cxB = cell_of(pxB, pm0, pr0), cyB = cell_of(pyB, pm1, pr1);

    for (int i = tid; i < NCAND; i += 256){
        int c = i / MPC;
        int rxA = min(max(cxA + c / 3 - 1, 0), GRID_C - 1);
        int ryA = min(max(cyA + c % 3 - 1, 0), GRID_C - 1);
        sm.candA[i] = cm_qk[(rxA * GRID_C + ryA) * MPC + (i & 31)];
        int rxB = min(max(cxB + c / 3 - 1, 0), GRID_C - 1);
        int ryB = min(max(cyB + c % 3 - 1, 0), GRID_C - 1);
        sm.candB[i] = cm_v[(rxB * GRID_C + ryB) * MPC + (i & 31)];
        sm.actA[i] = g_act[0][(size_t)token * NCAND + i];
        sm.actB[i] = g_act[1][(size_t)token * NCAND + i];
    }
    if (tid == 0){ sm.icntA = 0; sm.icntB = 0; }
    __syncthreads();

    if (w == 0)      warp_kth32(sm.actA, sm.candA, &sm.thr[0]);
    else if (w == 1) warp_kth32(sm.actB, sm.candB, &sm.thr[2]);
    __syncthreads();

    float tq = tau_Q[token], tk = tau_K[token], tvt = tau_V[token];
    float akA = sm.thr[0], mxA = sm.thr[1], akB = sm.thr[2], mxB = sm.thr[3];
    float tvQ = egf(akA, tq), tvK = egf(akA, tk), tvV = egf(akB, tvt);
    float stQ = tanhf(egf(mxA, tq)), stK = tanhf(egf(mxA, tk)), stV = tanhf(egf(mxB, tvt));

    float sQ = 0.f, sK = 0.f, sV = 0.f, sQpd = 0.f, sVpd = 0.f;
    for (int r = 0; r < 2; r++){
        int i = r * 256 + tid;
        bool keepA = false, keepB = false;
        float a = 0.f, b = 0.f, wQ = 0.f, wK = 0.f, wV = 0.f;
        int cA = -1, cB = -1;
        if (i < NCAND){
            cA = sm.candA[i];
            a  = sm.actA[i];
            float scA = (cA >= 0) ? a : -1e9f;
            float eQ = egf(scA, tq), eK = egf(scA, tk);
            float kq = (eQ >= tvQ) ? eQ : 0.f;
            float kk = (eK >= tvK) ? eK : 0.f;
            if (cA >= 0){
                wQ = kq; wK = kk;
                sQ += wQ; sK += wK;
                if (wQ > 0.f){
                    float dx = pxA - npos_qk[cA*2], dy = pyA - npos_qk[cA*2+1];
                    sQpd += wQ * (dx*dx + dy*dy);
                }
                keepA = (wQ != 0.f) || (wK != 0.f);
            }
            cB = sm.candB[i];
            b  = sm.actB[i];
            float scB = (cB >= 0) ? b : -1e9f;
            float eV = egf(scB, tvt);
            float kv = (eV >= tvV) ? eV : 0.f;
            if (cB >= 0){
                wV = kv;
                sV += wV;
                if (wV > 0.f){
                    float dx = pxB - npos_v[cB*2], dy = pyB - npos_v[cB*2+1];
                    sVpd += wV * (dx*dx + dy*dy);
                }
                keepB = (wV != 0.f);
            }
        }
        unsigned lt = (1u << ln) - 1u;
        unsigned balA = __ballot_sync(0xffffffffu, keepA);
        unsigned balB = __ballot_sync(0xffffffffu, keepB);
        int pA = __popc(balA & lt), pB = __popc(balB & lt);
        if (ln == 0){ sm.wcntA[w] = __popc(balA); sm.wcntB[w] = __popc(balB); }
        __syncthreads();
        if (tid == 0){
            int bA = sm.icntA, bB = sm.icntB;
            for (int w2 = 0; w2 < 8; w2++){
                int tA = sm.wcntA[w2]; sm.wcntA[w2] = bA; bA += tA;
                int tB = sm.wcntB[w2]; sm.wcntB[w2] = bB; bB += tB;
            }
            sm.icntA = bA; sm.icntB = bB;
        }
        __syncthreads();
        if (keepA){
            int p = sm.wcntA[w] + pA;
            sm.klA[p] = cA; sm.wq[p] = a * wQ; sm.wk[p] = a * wK;
        }
        if (keepB){
            int p = sm.wcntB[w] + pB;
            sm.klB[p] = cB; sm.wv[p] = b * wV;
        }
        __syncthreads();
    }
    #pragma unroll
    for (int o = 16; o; o >>= 1){
        sQ   += __shfl_xor_sync(0xffffffffu, sQ, o);
        sK   += __shfl_xor_sync(0xffffffffu, sK, o);
        sV   += __shfl_xor_sync(0xffffffffu, sV, o);
        sQpd += __shfl_xor_sync(0xffffffffu, sQpd, o);
        sVpd += __shfl_xor_sync(0xffffffffu, sVpd, o);
    }
    if (ln == 0){
        sm.redf[0][w] = sQ; sm.redf[1][w] = sK; sm.redf[2][w] = sV;
        sm.redf[3][w] = sQpd; sm.redf[4][w] = sVpd;
    }
    __syncthreads();
    if (tid == 0){
        float a0=0.f, a1=0.f, a2=0.f, a3=0.f, a4=0.f;
        for (int w2 = 0; w2 < 8; w2++){
            a0 += sm.redf[0][w2]; a1 += sm.redf[1][w2]; a2 += sm.redf[2][w2];
            a3 += sm.redf[3][w2]; a4 += sm.redf[4][w2];
        }
        float scQ = stQ / (a0 + 1e-8f);
        float scK = stK / (a1 + 1e-8f);
        float scV = stV / (a2 + 1e-8f);
        sm.sc[0] = scQ; sm.sc[1] = scK; sm.sc[2] = scV;
        g_posbuf[token] = scQ * a3;
        g_posbuf[NTOK + token] = scV * a4;
    }
    __syncthreads();
    {
        int nkA = sm.icntA;
        float scQ = sm.sc[0], scK = sm.sc[1];
        float2 q = make_float2(0.f, 0.f), k = make_float2(0.f, 0.f);
        #pragma unroll 4
        for (int j = 0; j < nkA; j++){
            const float2* row = (const float2*)(qk_neurons + (size_t)sm.klA[j] * ND);
            float cq = sm.wq[j] * scQ, ck = sm.wk[j] * scK;
            float2 r = row[tid];
            q.x += cq * r.x; q.y += cq * r.y;
            k.x += ck * r.x; k.y += ck * r.y;
        }
        ((float2*)(g_Q + (size_t)token * ND))[tid] = q;
        ((float2*)(g_K + (size_t)token * ND))[tid] = k;
    }
    {
        int nkB = sm.icntB;
        float scV = sm.sc[2];
        float2 v = make_float2(0.f, 0.f);
        #pragma unroll 4
        for (int j = 0; j < nkB; j++){
            const float2* row = (const float2*)(v_neurons + (size_t)sm.klB[j] * ND);
            float cv = sm.wv[j] * scV;
            float2 r = row[tid];
            v.x += cv * r.x; v.y += cv * r.y;
        }
        ((float2*)(g_V + (size_t)token * ND))[tid] = v;
    }
}

// ================= split-KV causal flash attention: 32q x 64kv, 128 threads =================
// 2 splits per (b,h,qt): halves the per-block critical path; partials merged exactly.
__global__ __launch_bounds__(128)
void attn_kernel(){
    __shared__ float QT[64][36];  // [d][q]
    __shared__ float Ks[64][68];  // [d][k]
    __shared__ float Vs[64][68];  // [t][d]
    int tid = threadIdx.x;
    int jj = blockIdx.x & 63;
    int qt = jj >> 1;
    int sp = jj & 1;
    int h  = (blockIdx.x >> 6) & 7;
    int b  = blockIdx.x >> 9;
    int q0 = qt * 32;
    int pb = ((b * NHEAD + h) << 5) | qt;
    int ntile = qt / 2 + 1;
    int hs = (ntile + 1) >> 1;
    int kts = sp ? hs : 0;
    int kte = sp ? ntile : hs;

    const float* Qg = g_Q + (size_t)b * NS * ND + h * DHEAD;
    const float* Kg = g_K + (size_t)b * NS * ND + h * DHEAD;
    const float* Vg = g_V + (size_t)b * NS * ND + h * DHEAD;

    int tx = tid & 15, ty = tid >> 4;
    int lane = tid & 31;
    float acc[4][4];
    float m[4], l[4];
    #pragma unroll
    for (int qi = 0; qi < 4; qi++){
        m[qi] = -FLT_MAX; l[qi] = 0.f;
        #pragma unroll
        for (int di = 0; di < 4; di++) acc[qi][di] = 0.f;
    }

    if (kts < kte){
        for (int i = tid; i < 32 * 64; i += 128){
            int r = i >> 6, c = i & 63;
            QT[c][r] = Qg[(size_t)(q0 + r) * ND + c];
        }
        for (int kt = kts; kt < kte; kt++){
            int t0 = kt * 64;
            __syncthreads();
            for (int i = tid; i < 64 * 64; i += 128){
                int r = i >> 6, c = i & 63;
                float kvv = Kg[(size_t)(t0 + r) * ND + c];
                float vvv = Vg[(size_t)(t0 + r) * ND + c];
                Ks[c][r] = kvv;
                Vs[r][c] = vvv;
            }
            __syncthreads();
            float sf[4][4];
            #pragma unroll
            for (int qi = 0; qi < 4; qi++)
                #pragma unroll
                for (int ki = 0; ki < 4; ki++) sf[qi][ki] = 0.f;
            #pragma unroll 4
            for (int d = 0; d < 64; d++){
                float4 qv = *(const float4*)&QT[d][ty * 4];
                float4 kv = *(const float4*)&Ks[d][tx * 4];
                float qa[4] = {qv.x, qv.y, qv.z, qv.w};
                float ka[4] = {kv.x, kv.y, kv.z, kv.w};
                #pragma unroll
                for (int qi = 0; qi < 4; qi++)
                    #pragma unroll
                    for (int ki = 0; ki < 4; ki++) sf[qi][ki] += qa[qi] * ka[ki];
            }
            const float scl = 0.125f;
            bool diag = (t0 + 64 > q0);
            float p[4][4];
            #pragma unroll
            for (int qi = 0; qi < 4; qi++){
                int qg = q0 + ty * 4 + qi;
                float rm = -FLT_MAX;
                #pragma unroll
                for (int ki = 0; ki < 4; ki++){
                    int tg = t0 + tx * 4 + ki;
                    float v = (!diag || tg <= qg) ? sf[qi][ki] * scl : -FLT_MAX;
                    p[qi][ki] = v;
                    rm = fmaxf(rm, v);
                }
                #pragma unroll
                for (int o = 1; o < 16; o <<= 1) rm = fmaxf(rm, __shfl_xor_sync(0xffffffffu, rm, o));
                float mn = fmaxf(m[qi], rm);
                float corr = expf(m[qi] - mn);
                float rs = 0.f;
                #pragma unroll
                for (int ki = 0; ki < 4; ki++){
                    float e = expf(p[qi][ki] - mn);
                    p[qi][ki] = e;
                    rs += e;
                }
                #pragma unroll
                for (int o = 1; o < 16; o <<= 1) rs += __shfl_xor_sync(0xffffffffu, rs, o);
                l[qi] = l[qi] * corr + rs;
                #pragma unroll
                for (int di = 0; di < 4; di++) acc[qi][di] *= corr;
                m[qi] = mn;
            }
            #pragma unroll 2
            for (int tg = 0; tg < 16; tg++){
                int src = (lane & 16) | tg;
                #pragma unroll
                for (int ki = 0; ki < 4; ki++){
                    int t = tg * 4 + ki;
                    float4 vv = *(const float4*)&Vs[t][tx * 4];
                    float pq0 = __shfl_sync(0xffffffffu, p[0][ki], src);
                    float pq1 = __shfl_sync(0xffffffffu, p[1][ki], src);
                    float pq2 = __shfl_sync(0xffffffffu, p[2][ki], src);
                    float pq3 = __shfl_sync(0xffffffffu, p[3][ki], src);
                    acc[0][0] += pq0 * vv.x; acc[0][1] += pq0 * vv.y; acc[0][2] += pq0 * vv.z; acc[0][3] += pq0 * vv.w;
                    acc[1][0] += pq1 * vv.x; acc[1][1] += pq1 * vv.y; acc[1][2] += pq1 * vv.z; acc[1][3] += pq1 * vv.w;
                    acc[2][0] += pq2 * vv.x; acc[2][1] += pq2 * vv.y; acc[2][2] += pq2 * vv.z; acc[2][3] += pq2 * vv.w;
                    acc[3][0] += pq3 * vv.x; acc[3][1] += pq3 * vv.y; acc[3][2] += pq3 * vv.z; acc[3][3] += pq3 * vv.w;
                }
            }
        }
    }
    // write partials (unnormalized acc, m, l)
    float* Pa = g_pacc[sp][pb];
    #pragma unroll
    for (int qi = 0; qi < 4; qi++){
        float4 o4;
        o4.x = acc[qi][0]; o4.y = acc[qi][1]; o4.z = acc[qi][2]; o4.w = acc[qi][3];
        *(float4*)&Pa[(ty * 4 + qi) * 64 + tx * 4] = o4;
    }
    if (tx == 0){
        #pragma unroll
        for (int qi = 0; qi < 4; qi++){
            g_pml[sp][pb][ty * 4 + qi] = m[qi];
            g_pml[sp][pb][32 + ty * 4 + qi] = l[qi];
        }
    }
}

// exact flash-merge of the two splits -> g_AO
__global__ __launch_bounds__(128)
void attn_merge(){
    int pb = blockIdx.x;
    int qt = pb & 31, h = (pb >> 5) & 7, b = pb >> 8;
    __shared__ float mlc[4][32];
    int tid = threadIdx.x;
    if (tid < 32){
        mlc[0][tid] = g_pml[0][pb][tid];
        mlc[1][tid] = g_pml[0][pb][32 + tid];
        mlc[2][tid] = g_pml[1][pb][tid];
        mlc[3][tid] = g_pml[1][pb][32 + tid];
    }
    __syncthreads();
    float* Og = g_AO + (size_t)b * NS * ND + h * DHEAD;
    for (int i = tid; i < 512; i += 128){
        int r = i >> 4, c4 = i & 15;
        float m0 = mlc[0][r], l0 = mlc[1][r], m1 = mlc[2][r], l1 = mlc[3][r];
        float mm = fmaxf(m0, m1);
        float c0 = expf(m0 - mm), c1 = expf(m1 - mm);
        float inv = 1.f / (l0 * c0 + l1 * c1);
        float4 a0 = *(float4*)&g_pacc[0][pb][r * 64 + c4 * 4];
        float4 a1 = *(float4*)&g_pacc[1][pb][r * 64 + c4 * 4];
        float4 o;
        o.x = (a0.x * c0 + a1.x * c1) * inv;
        o.y = (a0.y * c0 + a1.y * c1) * inv;
        o.z = (a0.z * c0 + a1.z * c1) * inv;
        o.w = (a0.w * c0 + a1.w * c1) * inv;
        *(float4*)&Og[(size_t)(qt * 32 + r) * ND + c4 * 4] = o;
    }
}

// final projection: out = g_AO[2048x512] @ expand_O[512x512]; block (0,0) also
// writes the pos_loss tail element.
__global__ __launch_bounds__(256)
void out_gemm(const float* __restrict__ Bmat, float* __restrict__ out, int has_tail){
    __shared__ float As[64][33];
    __shared__ float Bs[32][65];
    int tid = threadIdx.x;
    if (has_tail && blockIdx.x == 0 && blockIdx.y == 0){
        __shared__ float red[8];
        float s = 0.f;
        for (int i = tid; i < NTOK * 2; i += 256) s += g_posbuf[i];
        #pragma unroll
        for (int o = 16; o; o >>= 1) s += __shfl_xor_sync(0xffffffffu, s, o);
        if ((tid & 31) == 0) red[tid >> 5] = s;
        __syncthreads();
        if (tid == 0){
            float t = 0.f;
            for (int w = 0; w < 8; w++) t += red[w];
            out[(size_t)NTOK * ND] = t * (1.0f / (8.0f * 73728.0f));
        }
        __syncthreads();
    }
    int m0 = blockIdx.y * 64, n0 = blockIdx.x * 64;
    int tx = tid & 15, ty = tid >> 4;
    float acc[4][4];
    #pragma unroll
    for (int i = 0; i < 4; i++)
        #pragma unroll
        for (int j = 0; j < 4; j++) acc[i][j] = 0.f;
    for (int k0 = 0; k0 < ND; k0 += 32){
        __syncthreads();
        for (int i = tid; i < 64 * 32; i += 256){
            int r = i >> 5, c = i & 31;
            As[r][c] = g_AO[(size_t)(m0 + r) * ND + k0 + c];
        }
        for (int i = tid; i < 32 * 64; i += 256){
            int r = i >> 6, c = i & 63;
            Bs[r][c] = Bmat[(size_t)(k0 + r) * ND + n0 + c];
        }
        __syncthreads();
        #pragma unroll 8
        for (int k = 0; k < 32; k++){
            float a[4], bv[4];
            #pragma unroll
            for (int qi = 0; qi < 4; qi++) a[qi] = As[ty * 4 + qi][k];
            #pragma unroll
            for (int ni = 0; ni < 4; ni++) bv[ni] = Bs[k][tx * 4 + ni];
            #pragma unroll
            for (int qi = 0; qi < 4; qi++)
                #pragma unroll
                for (int ni = 0; ni < 4; ni++) acc[qi][ni] += a[qi] * bv[ni];
        }
    }
    #pragma unroll
    for (int qi = 0; qi < 4; qi++)
        #pragma unroll
        for (int ni = 0; ni < 4; ni++)
            out[(size_t)(m0 + ty * 4 + qi) * ND + n0 + tx * 4 + ni] = acc[qi][ni];
}

extern "C" void kernel_launch(void* const* d_in, const int* in_sizes, int n_in,
                              void* d_out, int out_size){
    const float* x          = (const float*)d_in[0];
    const float* qk_pos     = (const float*)d_in[1];
    const float* v_pos      = (const float*)d_in[2];
    const float* tau_Q      = (const float*)d_in[3];
    const float* tau_K      = (const float*)d_in[4];
    const float* tau_V      = (const float*)d_in[5];
    const float* qk_neurons = (const float*)d_in[6];
    const float* v_neurons  = (const float*)d_in[7];
    const float* npos_qk    = (const float*)d_in[8];
    const float* npos_v     = (const float*)d_in[9];
    const int*   cm_qk      = (const int*)d_in[10];
    const int*   cm_v       = (const int*)d_in[11];
    const float* pos_min    = (const float*)d_in[12];
    const float* pos_range  = (const float*)d_in[13];
    const float* expand_O   = (const float*)d_in[14];
    float* out = (float*)d_out;

    bin_all<<<1, 1024>>>(qk_pos, v_pos, pos_min, pos_range);
    dim3 sg(NCELL, 2);
    score_kernel<<<sg, 256>>>(x, qk_neurons, v_neurons, cm_qk, cm_v);
    gate_kernel<<<NTOK, 256>>>(qk_pos, v_pos, tau_Q, tau_K, tau_V,
                               qk_neurons, v_neurons, npos_qk, npos_v,
                               cm_qk, cm_v, pos_min, pos_range);
    attn_kernel<<<NB * NHEAD * 64, 128>>>();
    attn_merge<<<NPB, 128>>>();
    int has_tail = (out_size > NTOK * ND) ? 1 : 0;
    dim3 g(ND / 64, NTOK / 64);
    out_gemm<<<g, 256>>>(expand_O, out, has_tail);
}

// round 10
// speedup vs baseline: 1.2320x; 1.0197x over previous
#include <cuda_runtime.h>
#include <math.h>
#include <float.h>

#define NB 2
#define NS 1024
#define ND 512
#define NTOK (NB*NS)
#define NNEUR 4096
#define NCAND 288
#define MPC 32
#define GRID_C 16
#define NCELL (GRID_C*GRID_C)
#define NHEAD 8
#define DHEAD 64
#define NPB (NB*NHEAD*32)   // 512 (b,h,qt) tiles
#define NSPLIT 4
#define MAXCHUNK 1100

// ---------------- device scratch (static, no allocation) ----------------
__device__ float g_Q[NTOK*ND];
__device__ float g_K[NTOK*ND];
__device__ float g_V[NTOK*ND];
__device__ float g_AO[NTOK*ND];
__device__ float g_posbuf[NTOK*2];
__device__ float g_act[2][NTOK*NCAND];
__device__ int   g_off[2][NCELL+1];
__device__ int   g_list[2][NTOK];
__device__ float g_pacc[NSPLIT][NPB][32*64];
__device__ float g_pml[NSPLIT][NPB][64];
__device__ int   g_chunks[MAXCHUNK];   // packed: set<<24 | cell<<12 | local_start
__device__ int   g_nchunks;

// ---------------- helpers ----------------
__device__ __forceinline__ unsigned f2u(float f){
    unsigned u = __float_as_uint(f);
    return (u & 0x80000000u) ? ~u : (u | 0x80000000u);
}
__device__ __forceinline__ float u2f(unsigned u){
    u = (u & 0x80000000u) ? (u & 0x7FFFFFFFu) : ~u;
    return __uint_as_float(u);
}
__device__ __forceinline__ float egf(float score, float tau){
    float raw = score - tau;
    float gate = raw > 0.f ? raw : 1e-8f * expf(raw);
    return expf(gate) - 1.0f;
}
__device__ __forceinline__ int cell_of(float p, float pm, float pr){
    int c = (int)(((p - pm) / pr) * GRID_C);
    return min(max(c, 0), GRID_C - 1);
}

// ================= fused binning + chunk list: one block, one launch =================
__global__ __launch_bounds__(1024)
void bin_all(const float* __restrict__ qk_pos, const float* __restrict__ v_pos,
             const float* __restrict__ pos_min, const float* __restrict__ pos_range){
    __shared__ int cnt[2*NCELL];
    int tid = threadIdx.x;
    if (tid == 0) g_nchunks = 0;
    for (int i = tid; i < 2*NCELL; i += 1024) cnt[i] = 0;
    __syncthreads();
    float pm0 = pos_min[0], pm1 = pos_min[1], pr0 = pos_range[0], pr1 = pos_range[1];
    int c0[2], c1[2];
    #pragma unroll
    for (int r = 0; r < 2; r++){
        int t = tid + r * 1024;
        c0[r] = cell_of(qk_pos[t*2], pm0, pr0) * GRID_C + cell_of(qk_pos[t*2+1], pm1, pr1);
        c1[r] = cell_of(v_pos[t*2],  pm0, pr0) * GRID_C + cell_of(v_pos[t*2+1],  pm1, pr1);
        atomicAdd(&cnt[c0[r]], 1);
        atomicAdd(&cnt[NCELL + c1[r]], 1);
    }
    __syncthreads();
    if (tid < 2){
        int acc = 0;
        for (int c = 0; c < NCELL; c++){ g_off[tid][c] = acc; acc += cnt[tid*NCELL + c]; }
        g_off[tid][NCELL] = acc;
    }
    __syncthreads();
    // build uniform 8-token chunk worklist (order benign: disjoint deterministic writes)
    if (tid < 2*NCELL){
        int set = tid >> 8, cell = tid & 255;
        int s = g_off[set][cell], e = g_off[set][cell+1];
        for (int c = s; c < e; c += 8){
            int idx = atomicAdd(&g_nchunks, 1);
            g_chunks[idx] = (set << 24) | (cell << 12) | (c - s);
        }
    }
    for (int i = tid; i < 2*NCELL; i += 1024) cnt[i] = 0;
    __syncthreads();
    #pragma unroll
    for (int r = 0; r < 2; r++){
        int t = tid + r * 1024;
        int p0 = atomicAdd(&cnt[c0[r]], 1);
        g_list[0][g_off[0][c0[r]] + p0] = t;
        int p1 = atomicAdd(&cnt[NCELL + c1[r]], 1);
        g_list[1][g_off[1][c1[r]] + p1] = t;
    }
}

// ================= chunked candidate scoring: uniform 8-token chunks =================
__global__ __launch_bounds__(256)
void score_kernel(const float* __restrict__ x,
                  const float* __restrict__ qk_neurons, const float* __restrict__ v_neurons,
                  const int* __restrict__ cm_qk, const int* __restrict__ cm_v){
    __shared__ float xs[8][ND];
    __shared__ int cand[NCAND];
    __shared__ int toks[8];
    int tid = threadIdx.x;
    int w = tid >> 5, ln = tid & 31;
    int nch = g_nchunks;
    for (int ci = blockIdx.x; ci < nch; ci += gridDim.x){
        int pk = g_chunks[ci];
        int set = pk >> 24, cell = (pk >> 12) & 0xFFF, ls = pk & 0xFFF;
        const float* neur = set ? v_neurons : qk_neurons;
        const int*   cmap = set ? cm_v : cm_qk;
        int start = g_off[set][cell] + ls;
        int end = min(start + 8, g_off[set][cell+1]);
        __syncthreads();
        for (int i = tid; i < NCAND; i += 256){
            int cx = cell >> 4, cy = cell & 15;
            int c = i / MPC;
            int rx = min(max(cx + c / 3 - 1, 0), GRID_C - 1);
            int ry = min(max(cy + c % 3 - 1, 0), GRID_C - 1);
            int id = cmap[(rx * GRID_C + ry) * MPC + (i & 31)];
            cand[i] = id < 0 ? 0 : id;
        }
        if (tid < 8) toks[tid] = g_list[set][min(start + tid, end - 1)];
        __syncthreads();
        for (int i = tid; i < 8 * (ND/4); i += 256){
            int t = i >> 7, e = i & 127;
            ((float4*)&xs[t][0])[e] = ((const float4*)(x + (size_t)toks[t] * ND))[e];
        }
        __syncthreads();
        float xr[8][16];
        #pragma unroll
        for (int t = 0; t < 8; t++)
            #pragma unroll
            for (int e = 0; e < 16; e++) xr[t][e] = xs[t][e * 32 + ln];
        for (int i = w; i < NCAND; i += 8){
            const float* row = neur + (size_t)cand[i] * ND;
            float a[8];
            #pragma unroll
            for (int t = 0; t < 8; t++) a[t] = 0.f;
            #pragma unroll
            for (int e = 0; e < 16; e++){
                float r = row[e * 32 + ln];
                #pragma unroll
                for (int t = 0; t < 8; t++) a[t] += r * xr[t][e];
            }
            #pragma unroll
            for (int o = 16; o; o >>= 1){
                #pragma unroll
                for (int t = 0; t < 8; t++) a[t] += __shfl_xor_sync(0xffffffffu, a[t], o);
            }
            if (ln == 0){
                #pragma unroll
                for (int t = 0; t < 8; t++)
                    if (start + t < end) g_act[set][(size_t)toks[t] * NCAND + i] = a[t];
            }
        }
    }
}

// ================= per-token gating + weighted gather =================
struct GSmem {
    float actA[NCAND]; float actB[NCAND];
    int   candA[NCAND]; int candB[NCAND];
    float wq[NCAND], wk[NCAND], wv[NCAND];
    int   klA[NCAND], klB[NCAND];
    float thr[4];
    float redf[5][8];
    int   wcntA[8], wcntB[8];
    int   icntA, icntB;
    float sc[3];
};

// single-warp exact 32nd-largest (counting duplicates) via bitwise binary search
__device__ __forceinline__ void warp_kth32(const float* act, const int* cand, float* out2){
    int ln = threadIdx.x & 31;
    unsigned vu[9]; unsigned mxu = 0;
    #pragma unroll
    for (int j = 0; j < 9; j++){
        int idx = ln + j * 32;
        float v = (cand[idx] >= 0) ? act[idx] : -1e9f;
        unsigned u = f2u(v);
        vu[j] = u;
        mxu = max(mxu, u);
    }
    mxu = __reduce_max_sync(0xffffffffu, mxu);
    unsigned T = 0u;
    #pragma unroll
    for (int bit = 31; bit >= 0; bit--){
        unsigned Tc = T | (1u << bit);
        int c = 0;
        #pragma unroll
        for (int j = 0; j < 9; j++) c += (vu[j] >= Tc) ? 1 : 0;
        c = __reduce_add_sync(0xffffffffu, c);
        if (c >= 32) T = Tc;
    }
    if (ln == 0){ out2[0] = u2f(T); out2[1] = u2f(mxu); }
}

__global__ __launch_bounds__(256)
void gate_kernel(const float* __restrict__ qk_pos, const float* __restrict__ v_pos,
                 const float* __restrict__ tau_Q, const float* __restrict__ tau_K,
                 const float* __restrict__ tau_V,
                 const float* __restrict__ qk_neurons, const float* __restrict__ v_neurons,
                 const float* __restrict__ npos_qk, const float* __restrict__ npos_v,
                 const int* __restrict__ cm_qk, const int* __restrict__ cm_v,
                 const float* __restrict__ pos_min, const float* __restrict__ pos_range)
{
    __shared__ GSmem sm;
    int token = blockIdx.x;
    int tid = threadIdx.x;
    int w = tid >> 5, ln = tid & 31;
    float pm0 = pos_min[0], pm1 = pos_min[1];
    float pr0 = pos_range[0], pr1 = pos_range[1];

    float pxA = qk_pos[token*2], pyA = qk_pos[token*2+1];
    float pxB = v_pos[token*2],  pyB = v_pos[token*2+1];
    int cxA = cell_of(pxA, pm0, pr0), cyA = cell_of(pyA, pm1, pr1);
    int cxB = cell_of(pxB, pm0, pr0), cyB = cell_of(pyB, pm1, pr1);

    for (int i = tid; i < NCAND; i += 256){
        int c = i / MPC;
        int rxA = min(max(cxA + c / 3 - 1, 0), GRID_C - 1);
        int ryA = min(max(cyA + c % 3 - 1, 0), GRID_C - 1);
        sm.candA[i] = cm_qk[(rxA * GRID_C + ryA) * MPC + (i & 31)];
        int rxB = min(max(cxB + c / 3 - 1, 0), GRID_C - 1);
        int ryB = min(max(cyB + c % 3 - 1, 0), GRID_C - 1);
        sm.candB[i] = cm_v[(rxB * GRID_C + ryB) * MPC + (i & 31)];
        sm.actA[i] = g_act[0][(size_t)token * NCAND + i];
        sm.actB[i] = g_act[1][(size_t)token * NCAND + i];
    }
    if (tid == 0){ sm.icntA = 0; sm.icntB = 0; }
    __syncthreads();

    if (w == 0)      warp_kth32(sm.actA, sm.candA, &sm.thr[0]);
    else if (w == 1) warp_kth32(sm.actB, sm.candB, &sm.thr[2]);
    __syncthreads();

    float tq = tau_Q[token], tk = tau_K[token], tvt = tau_V[token];
    float akA = sm.thr[0], mxA = sm.thr[1], akB = sm.thr[2], mxB = sm.thr[3];
    float tvQ = egf(akA, tq), tvK = egf(akA, tk), tvV = egf(akB, tvt);
    float stQ = tanhf(egf(mxA, tq)), stK = tanhf(egf(mxA, tk)), stV = tanhf(egf(mxB, tvt));

    float sQ = 0.f, sK = 0.f, sV = 0.f, sQpd = 0.f, sVpd = 0.f;
    for (int r = 0; r < 2; r++){
        int i = r * 256 + tid;
        bool keepA = false, keepB = false;
        float a = 0.f, b = 0.f, wQ = 0.f, wK = 0.f, wV = 0.f;
        int cA = -1, cB = -1;
        if (i < NCAND){
            cA = sm.candA[i];
            a  = sm.actA[i];
            float scA = (cA >= 0) ? a : -1e9f;
            float eQ = egf(scA, tq), eK = egf(scA, tk);
            float kq = (eQ >= tvQ) ? eQ : 0.f;
            float kk = (eK >= tvK) ? eK : 0.f;
            if (cA >= 0){
                wQ = kq; wK = kk;
                sQ += wQ; sK += wK;
                if (wQ > 0.f){
                    float dx = pxA - npos_qk[cA*2], dy = pyA - npos_qk[cA*2+1];
                    sQpd += wQ * (dx*dx + dy*dy);
                }
                keepA = (wQ != 0.f) || (wK != 0.f);
            }
            cB = sm.candB[i];
            b  = sm.actB[i];
            float scB = (cB >= 0) ? b : -1e9f;
            float eV = egf(scB, tvt);
            float kv = (eV >= tvV) ? eV : 0.f;
            if (cB >= 0){
                wV = kv;
                sV += wV;
                if (wV > 0.f){
                    float dx = pxB - npos_v[cB*2], dy = pyB - npos_v[cB*2+1];
                    sVpd += wV * (dx*dx + dy*dy);
                }
                keepB = (wV != 0.f);
            }
        }
        unsigned lt = (1u << ln) - 1u;
        unsigned balA = __ballot_sync(0xffffffffu, keepA);
        unsigned balB = __ballot_sync(0xffffffffu, keepB);
        int pA = __popc(balA & lt), pB = __popc(balB & lt);
        if (ln == 0){ sm.wcntA[w] = __popc(balA); sm.wcntB[w] = __popc(balB); }
        __syncthreads();
        if (tid == 0){
            int bA = sm.icntA, bB = sm.icntB;
            for (int w2 = 0; w2 < 8; w2++){
                int tA = sm.wcntA[w2]; sm.wcntA[w2] = bA; bA += tA;
                int tB = sm.wcntB[w2]; sm.wcntB[w2] = bB; bB += tB;
            }
            sm.icntA = bA; sm.icntB = bB;
        }
        __syncthreads();
        if (keepA){
            int p = sm.wcntA[w] + pA;
            sm.klA[p] = cA; sm.wq[p] = a * wQ; sm.wk[p] = a * wK;
        }
        if (keepB){
            int p = sm.wcntB[w] + pB;
            sm.klB[p] = cB; sm.wv[p] = b * wV;
        }
        __syncthreads();
    }
    #pragma unroll
    for (int o = 16; o; o >>= 1){
        sQ   += __shfl_xor_sync(0xffffffffu, sQ, o);
        sK   += __shfl_xor_sync(0xffffffffu, sK, o);
        sV   += __shfl_xor_sync(0xffffffffu, sV, o);
        sQpd += __shfl_xor_sync(0xffffffffu, sQpd, o);
        sVpd += __shfl_xor_sync(0xffffffffu, sVpd, o);
    }
    if (ln == 0){
        sm.redf[0][w] = sQ; sm.redf[1][w] = sK; sm.redf[2][w] = sV;
        sm.redf[3][w] = sQpd; sm.redf[4][w] = sVpd;
    }
    __syncthreads();
    if (tid == 0){
        float a0=0.f, a1=0.f, a2=0.f, a3=0.f, a4=0.f;
        for (int w2 = 0; w2 < 8; w2++){
            a0 += sm.redf[0][w2]; a1 += sm.redf[1][w2]; a2 += sm.redf[2][w2];
            a3 += sm.redf[3][w2]; a4 += sm.redf[4][w2];
        }
        float scQ = stQ / (a0 + 1e-8f);
        float scK = stK / (a1 + 1e-8f);
        float scV = stV / (a2 + 1e-8f);
        sm.sc[0] = scQ; sm.sc[1] = scK; sm.sc[2] = scV;
        g_posbuf[token] = scQ * a3;
        g_posbuf[NTOK + token] = scV * a4;
    }
    __syncthreads();
    {
        int nkA = sm.icntA;
        float scQ = sm.sc[0], scK = sm.sc[1];
        float2 q = make_float2(0.f, 0.f), k = make_float2(0.f, 0.f);
        #pragma unroll 4
        for (int j = 0; j < nkA; j++){
            const float2* row = (const float2*)(qk_neurons + (size_t)sm.klA[j] * ND);
            float cq = sm.wq[j] * scQ, ck = sm.wk[j] * scK;
            float2 r = row[tid];
            q.x += cq * r.x; q.y += cq * r.y;
            k.x += ck * r.x; k.y += ck * r.y;
        }
        ((float2*)(g_Q + (size_t)token * ND))[tid] = q;
        ((float2*)(g_K + (size_t)token * ND))[tid] = k;
    }
    {
        int nkB = sm.icntB;
        float scV = sm.sc[2];
        float2 v = make_float2(0.f, 0.f);
        #pragma unroll 4
        for (int j = 0; j < nkB; j++){
            const float2* row = (const float2*)(v_neurons + (size_t)sm.klB[j] * ND);
            float cv = sm.wv[j] * scV;
            float2 r = row[tid];
            v.x += cv * r.x; v.y += cv * r.y;
        }
        ((float2*)(g_V + (size_t)token * ND))[tid] = v;
    }
}

// ================= 4-way split-KV causal flash attention =================
__global__ __launch_bounds__(128)
void attn_kernel(){
    __shared__ float QT[64][36];  // [d][q]
    __shared__ float Ks[64][68];  // [d][k]
    __shared__ float Vs[64][68];  // [t][d]
    int tid = threadIdx.x;
    int jj = blockIdx.x & 127;
    int qt = jj >> 2;
    int sp = jj & 3;
    int h  = (blockIdx.x >> 7) & 7;
    int b  = blockIdx.x >> 10;
    int q0 = qt * 32;
    int pb = ((b * NHEAD + h) << 5) | qt;
    int ntile = qt / 2 + 1;
    int kts = sp * ntile / NSPLIT;
    int kte = (sp + 1) * ntile / NSPLIT;

    const float* Qg = g_Q + (size_t)b * NS * ND + h * DHEAD;
    const float* Kg = g_K + (size_t)b * NS * ND + h * DHEAD;
    const float* Vg = g_V + (size_t)b * NS * ND + h * DHEAD;

    int tx = tid & 15, ty = tid >> 4;
    int lane = tid & 31;
    float acc[4][4];
    float m[4], l[4];
    #pragma unroll
    for (int qi = 0; qi < 4; qi++){
        m[qi] = -FLT_MAX; l[qi] = 0.f;
        #pragma unroll
        for (int di = 0; di < 4; di++) acc[qi][di] = 0.f;
    }

    if (kts < kte){
        for (int i = tid; i < 32 * 64; i += 128){
            int r = i >> 6, c = i & 63;
            QT[c][r] = Qg[(size_t)(q0 + r) * ND + c];
        }
        for (int kt = kts; kt < kte; kt++){
            int t0 = kt * 64;
            __syncthreads();
            for (int i = tid; i < 64 * 64; i += 128){
                int r = i >> 6, c = i & 63;
                float kvv = Kg[(size_t)(t0 + r) * ND + c];
                float vvv = Vg[(size_t)(t0 + r) * ND + c];
                Ks[c][r] = kvv;
                Vs[r][c] = vvv;
            }
            __syncthreads();
            float sf[4][4];
            #pragma unroll
            for (int qi = 0; qi < 4; qi++)
                #pragma unroll
                for (int ki = 0; ki < 4; ki++) sf[qi][ki] = 0.f;
            #pragma unroll 4
            for (int d = 0; d < 64; d++){
                float4 qv = *(const float4*)&QT[d][ty * 4];
                float4 kv = *(const float4*)&Ks[d][tx * 4];
                float qa[4] = {qv.x, qv.y, qv.z, qv.w};
                float ka[4] = {kv.x, kv.y, kv.z, kv.w};
                #pragma unroll
                for (int qi = 0; qi < 4; qi++)
                    #pragma unroll
                    for (int ki = 0; ki < 4; ki++) sf[qi][ki] += qa[qi] * ka[ki];
            }
            const float scl = 0.125f;
            bool diag = (t0 + 64 > q0);
            float p[4][4];
            #pragma unroll
            for (int qi = 0; qi < 4; qi++){
                int qg = q0 + ty * 4 + qi;
                float rm = -FLT_MAX;
                #pragma unroll
                for (int ki = 0; ki < 4; ki++){
                    int tg = t0 + tx * 4 + ki;
                    float v = (!diag || tg <= qg) ? sf[qi][ki] * scl : -FLT_MAX;
                    p[qi][ki] = v;
                    rm = fmaxf(rm, v);
                }
                #pragma unroll
                for (int o = 1; o < 16; o <<= 1) rm = fmaxf(rm, __shfl_xor_sync(0xffffffffu, rm, o));
                float mn = fmaxf(m[qi], rm);
                float corr = expf(m[qi] - mn);
                float rs = 0.f;
                #pragma unroll
                for (int ki = 0; ki < 4; ki++){
                    float e = expf(p[qi][ki] - mn);
                    p[qi][ki] = e;
                    rs += e;
                }
                #pragma unroll
                for (int o = 1; o < 16; o <<= 1) rs += __shfl_xor_sync(0xffffffffu, rs, o);
                l[qi] = l[qi] * corr + rs;
                #pragma unroll
                for (int di = 0; di < 4; di++) acc[qi][di] *= corr;
                m[qi] = mn;
            }
            #pragma unroll 2
            for (int tg = 0; tg < 16; tg++){
                int src = (lane & 16) | tg;
                #pragma unroll
                for (int ki = 0; ki < 4; ki++){
                    int t = tg * 4 + ki;
                    float4 vv = *(const float4*)&Vs[t][tx * 4];
                    float pq0 = __shfl_sync(0xffffffffu, p[0][ki], src);
                    float pq1 = __shfl_sync(0xffffffffu, p[1][ki], src);
                    float pq2 = __shfl_sync(0xffffffffu, p[2][ki], src);
                    float pq3 = __shfl_sync(0xffffffffu, p[3][ki], src);
                    acc[0][0] += pq0 * vv.x; acc[0][1] += pq0 * vv.y; acc[0][2] += pq0 * vv.z; acc[0][3] += pq0 * vv.w;
                    acc[1][0] += pq1 * vv.x; acc[1][1] += pq1 * vv.y; acc[1][2] += pq1 * vv.z; acc[1][3] += pq1 * vv.w;
                    acc[2][0] += pq2 * vv.x; acc[2][1] += pq2 * vv.y; acc[2][2] += pq2 * vv.z; acc[2][3] += pq2 * vv.w;
                    acc[3][0] += pq3 * vv.x; acc[3][1] += pq3 * vv.y; acc[3][2] += pq3 * vv.z; acc[3][3] += pq3 * vv.w;
                }
            }
        }
    }
    float* Pa = g_pacc[sp][pb];
    #pragma unroll
    for (int qi = 0; qi < 4; qi++){
        float4 o4;
        o4.x = acc[qi][0]; o4.y = acc[qi][1]; o4.z = acc[qi][2]; o4.w = acc[qi][3];
        *(float4*)&Pa[(ty * 4 + qi) * 64 + tx * 4] = o4;
    }
    if (tx == 0){
        #pragma unroll
        for (int qi = 0; qi < 4; qi++){
            g_pml[sp][pb][ty * 4 + qi] = m[qi];
            g_pml[sp][pb][32 + ty * 4 + qi] = l[qi];
        }
    }
}

// exact 4-way flash-merge of splits -> g_AO
__global__ __launch_bounds__(128)
void attn_merge(){
    int pb = blockIdx.x;
    int qt = pb & 31, h = (pb >> 5) & 7, b = pb >> 8;
    __shared__ float mlc[8][32];
    int tid = threadIdx.x;
    if (tid < 32){
        #pragma unroll
        for (int s = 0; s < NSPLIT; s++){
            mlc[s][tid] = g_pml[s][pb][tid];
            mlc[NSPLIT + s][tid] = g_pml[s][pb][32 + tid];
        }
    }
    __syncthreads();
    float* Og = g_AO + (size_t)b * NS * ND + h * DHEAD;
    for (int i = tid; i < 512; i += 128){
        int r = i >> 4, c4 = i & 15;
        float mm = -FLT_MAX;
        #pragma unroll
        for (int s = 0; s < NSPLIT; s++) mm = fmaxf(mm, mlc[s][r]);
        float cs[NSPLIT]; float den = 0.f;
        #pragma unroll
        for (int s = 0; s < NSPLIT; s++){
            cs[s] = expf(mlc[s][r] - mm);
            den += mlc[NSPLIT + s][r] * cs[s];
        }
        float inv = 1.f / den;
        float4 o = make_float4(0.f, 0.f, 0.f, 0.f);
        #pragma unroll
        for (int s = 0; s < NSPLIT; s++){
            float4 a = *(float4*)&g_pacc[s][pb][r * 64 + c4 * 4];
            o.x += a.x * cs[s]; o.y += a.y * cs[s];
            o.z += a.z * cs[s]; o.w += a.w * cs[s];
        }
        o.x *= inv; o.y *= inv; o.z *= inv; o.w *= inv;
        *(float4*)&Og[(size_t)(qt * 32 + r) * ND + c4 * 4] = o;
    }
}

// final projection: out = g_AO[2048x512] @ expand_O[512x512]; block (0,0) also
// writes the pos_loss tail element.
__global__ __launch_bounds__(256)
void out_gemm(const float* __restrict__ Bmat, float* __restrict__ out, int has_tail){
    __shared__ float As[64][33];
    __shared__ float Bs[32][65];
    int tid = threadIdx.x;
    if (has_tail && blockIdx.x == 0 && blockIdx.y == 0){
        __shared__ float red[8];
        float s = 0.f;
        for (int i = tid; i < NTOK * 2; i += 256) s += g_posbuf[i];
        #pragma unroll
        for (int o = 16; o; o >>= 1) s += __shfl_xor_sync(0xffffffffu, s, o);
        if ((tid & 31) == 0) red[tid >> 5] = s;
        __syncthreads();
        if (tid == 0){
            float t = 0.f;
            for (int w = 0; w < 8; w++) t += red[w];
            out[(size_t)NTOK * ND] = t * (1.0f / (8.0f * 73728.0f));
        }
        __syncthreads();
    }
    int m0 = blockIdx.y * 64, n0 = blockIdx.x * 64;
    int tx = tid & 15, ty = tid >> 4;
    float acc[4][4];
    #pragma unroll
    for (int i = 0; i < 4; i++)
        #pragma unroll
        for (int j = 0; j < 4; j++) acc[i][j] = 0.f;
    for (int k0 = 0; k0 < ND; k0 += 32){
        __syncthreads();
        for (int i = tid; i < 64 * 32; i += 256){
            int r = i >> 5, c = i & 31;
            As[r][c] = g_AO[(size_t)(m0 + r) * ND + k0 + c];
        }
        for (int i = tid; i < 32 * 64; i += 256){
            int r = i >> 6, c = i & 63;
            Bs[r][c] = Bmat[(size_t)(k0 + r) * ND + n0 + c];
        }
        __syncthreads();
        #pragma unroll 8
        for (int k = 0; k < 32; k++){
            float a[4], bv[4];
            #pragma unroll
            for (int qi = 0; qi < 4; qi++) a[qi] = As[ty * 4 + qi][k];
            #pragma unroll
            for (int ni = 0; ni < 4; ni++) bv[ni] = Bs[k][tx * 4 + ni];
            #pragma unroll
            for (int qi = 0; qi < 4; qi++)
                #pragma unroll
                for (int ni = 0; ni < 4; ni++) acc[qi][ni] += a[qi] * bv[ni];
        }
    }
    #pragma unroll
    for (int qi = 0; qi < 4; qi++)
        #pragma unroll
        for (int ni = 0; ni < 4; ni++)
            out[(size_t)(m0 + ty * 4 + qi) * ND + n0 + tx * 4 + ni] = acc[qi][ni];
}

extern "C" void kernel_launch(void* const* d_in, const int* in_sizes, int n_in,
                              void* d_out, int out_size){
    const float* x          = (const float*)d_in[0];
    const float* qk_pos     = (const float*)d_in[1];
    const float* v_pos      = (const float*)d_in[2];
    const float* tau_Q      = (const float*)d_in[3];
    const float* tau_K      = (const float*)d_in[4];
    const float* tau_V      = (const float*)d_in[5];
    const float* qk_neurons = (const float*)d_in[6];
    const float* v_neurons  = (const float*)d_in[7];
    const float* npos_qk    = (const float*)d_in[8];
    const float* npos_v     = (const float*)d_in[9];
    const int*   cm_qk      = (const int*)d_in[10];
    const int*   cm_v       = (const int*)d_in[11];
    const float* pos_min    = (const float*)d_in[12];
    const float* pos_range  = (const float*)d_in[13];
    const float* expand_O   = (const float*)d_in[14];
    float* out = (float*)d_out;

    bin_all<<<1, 1024>>>(qk_pos, v_pos, pos_min, pos_range);
    score_kernel<<<1024, 256>>>(x, qk_neurons, v_neurons, cm_qk, cm_v);
    gate_kernel<<<NTOK, 256>>>(qk_pos, v_pos, tau_Q, tau_K, tau_V,
                               qk_neurons, v_neurons, npos_qk, npos_v,
                               cm_qk, cm_v, pos_min, pos_range);
    attn_kernel<<<NB * NHEAD * 32 * NSPLIT, 128>>>();
    attn_merge<<<NPB, 128>>>();
    int has_tail = (out_size > NTOK * ND) ? 1 : 0;
    dim3 g(ND / 64, NTOK / 64);
    out_gemm<<<g, 256>>>(expand_O, out, has_tail);
}

// round 11
// speedup vs baseline: 1.2635x; 1.0256x over previous
#include <cuda_runtime.h>
#include <math.h>
#include <float.h>

#define NB 2
#define NS 1024
#define ND 512
#define NTOK (NB*NS)
#define NNEUR 4096
#define NCAND 288
#define MPC 32
#define GRID_C 16
#define NCELL (GRID_C*GRID_C)
#define NHEAD 8
#define DHEAD 64
#define NPB (NB*NHEAD*32)
#define NSPLIT 4
#define MAXCHUNK 1100

// ---------------- device scratch (static, no allocation) ----------------
__device__ float g_Q[NTOK*ND];
__device__ float g_K[NTOK*ND];
__device__ float g_V[NTOK*ND];
__device__ float g_AO[NTOK*ND];
__device__ float g_posbuf[NTOK*2];
__device__ float g_act[2][NTOK*NCAND];
__device__ int   g_off[2][NCELL+1];
__device__ int   g_list[2][NTOK];
__device__ float g_pacc[NSPLIT][NPB][32*64];
__device__ float g_pml[NSPLIT][NPB][64];
__device__ int   g_chunks[MAXCHUNK];
__device__ int   g_nchunks;

// ---------------- helpers ----------------
__device__ __forceinline__ unsigned f2u(float f){
    unsigned u = __float_as_uint(f);
    return (u & 0x80000000u) ? ~u : (u | 0x80000000u);
}
__device__ __forceinline__ float u2f(unsigned u){
    u = (u & 0x80000000u) ? (u & 0x7FFFFFFFu) : ~u;
    return __uint_as_float(u);
}
__device__ __forceinline__ float egf(float score, float tau){
    float raw = score - tau;
    float gate = raw > 0.f ? raw : 1e-8f * expf(raw);
    return expf(gate) - 1.0f;
}
__device__ __forceinline__ int cell_of(float p, float pm, float pr){
    int c = (int)(((p - pm) / pr) * GRID_C);
    return min(max(c, 0), GRID_C - 1);
}
#define CVT_TF32(d, s) asm("cvt.rna.tf32.f32 %0, %1;" : "=r"(d) : "f"(s))

// ================= fused binning + chunk list =================
__global__ __launch_bounds__(1024)
void bin_all(const float* __restrict__ qk_pos, const float* __restrict__ v_pos,
             const float* __restrict__ pos_min, const float* __restrict__ pos_range){
    __shared__ int cnt[2*NCELL];
    int tid = threadIdx.x;
    if (tid == 0) g_nchunks = 0;
    for (int i = tid; i < 2*NCELL; i += 1024) cnt[i] = 0;
    __syncthreads();
    float pm0 = pos_min[0], pm1 = pos_min[1], pr0 = pos_range[0], pr1 = pos_range[1];
    int c0[2], c1[2];
    #pragma unroll
    for (int r = 0; r < 2; r++){
        int t = tid + r * 1024;
        c0[r] = cell_of(qk_pos[t*2], pm0, pr0) * GRID_C + cell_of(qk_pos[t*2+1], pm1, pr1);
        c1[r] = cell_of(v_pos[t*2],  pm0, pr0) * GRID_C + cell_of(v_pos[t*2+1],  pm1, pr1);
        atomicAdd(&cnt[c0[r]], 1);
        atomicAdd(&cnt[NCELL + c1[r]], 1);
    }
    __syncthreads();
    if (tid < 2){
        int acc = 0;
        for (int c = 0; c < NCELL; c++){ g_off[tid][c] = acc; acc += cnt[tid*NCELL + c]; }
        g_off[tid][NCELL] = acc;
    }
    __syncthreads();
    if (tid < 2*NCELL){
        int set = tid >> 8, cell = tid & 255;
        int s = g_off[set][cell], e = g_off[set][cell+1];
        for (int c = s; c < e; c += 8){
            int idx = atomicAdd(&g_nchunks, 1);
            g_chunks[idx] = (set << 24) | (cell << 12) | (c - s);
        }
    }
    for (int i = tid; i < 2*NCELL; i += 1024) cnt[i] = 0;
    __syncthreads();
    #pragma unroll
    for (int r = 0; r < 2; r++){
        int t = tid + r * 1024;
        int p0 = atomicAdd(&cnt[c0[r]], 1);
        g_list[0][g_off[0][c0[r]] + p0] = t;
        int p1 = atomicAdd(&cnt[NCELL + c1[r]], 1);
        g_list[1][g_off[1][c1[r]] + p1] = t;
    }
}

// ================= chunked candidate scoring =================
__global__ __launch_bounds__(256)
void score_kernel(const float* __restrict__ x,
                  const float* __restrict__ qk_neurons, const float* __restrict__ v_neurons,
                  const int* __restrict__ cm_qk, const int* __restrict__ cm_v){
    __shared__ float xs[8][ND];
    __shared__ int cand[NCAND];
    __shared__ int toks[8];
    int tid = threadIdx.x;
    int w = tid >> 5, ln = tid & 31;
    int nch = g_nchunks;
    for (int ci = blockIdx.x; ci < nch; ci += gridDim.x){
        int pk = g_chunks[ci];
        int set = pk >> 24, cell = (pk >> 12) & 0xFFF, ls = pk & 0xFFF;
        const float* neur = set ? v_neurons : qk_neurons;
        const int*   cmap = set ? cm_v : cm_qk;
        int start = g_off[set][cell] + ls;
        int end = min(start + 8, g_off[set][cell+1]);
        __syncthreads();
        for (int i = tid; i < NCAND; i += 256){
            int cx = cell >> 4, cy = cell & 15;
            int c = i / MPC;
            int rx = min(max(cx + c / 3 - 1, 0), GRID_C - 1);
            int ry = min(max(cy + c % 3 - 1, 0), GRID_C - 1);
            int id = cmap[(rx * GRID_C + ry) * MPC + (i & 31)];
            cand[i] = id < 0 ? 0 : id;
        }
        if (tid < 8) toks[tid] = g_list[set][min(start + tid, end - 1)];
        __syncthreads();
        for (int i = tid; i < 8 * (ND/4); i += 256){
            int t = i >> 7, e = i & 127;
            ((float4*)&xs[t][0])[e] = ((const float4*)(x + (size_t)toks[t] * ND))[e];
        }
        __syncthreads();
        float xr[8][16];
        #pragma unroll
        for (int t = 0; t < 8; t++)
            #pragma unroll
            for (int e = 0; e < 16; e++) xr[t][e] = xs[t][e * 32 + ln];
        for (int i = w; i < NCAND; i += 8){
            const float* row = neur + (size_t)cand[i] * ND;
            float a[8];
            #pragma unroll
            for (int t = 0; t < 8; t++) a[t] = 0.f;
            #pragma unroll
            for (int e = 0; e < 16; e++){
                float r = row[e * 32 + ln];
                #pragma unroll
                for (int t = 0; t < 8; t++) a[t] += r * xr[t][e];
            }
            #pragma unroll
            for (int o = 16; o; o >>= 1){
                #pragma unroll
                for (int t = 0; t < 8; t++) a[t] += __shfl_xor_sync(0xffffffffu, a[t], o);
            }
            if (ln == 0){
                #pragma unroll
                for (int t = 0; t < 8; t++)
                    if (start + t < end) g_act[set][(size_t)toks[t] * NCAND + i] = a[t];
            }
        }
    }
}

// ================= per-token gating + weighted gather =================
struct GSmem {
    float actA[NCAND]; float actB[NCAND];
    int   candA[NCAND]; int candB[NCAND];
    float wq[NCAND], wk[NCAND], wv[NCAND];
    int   klA[NCAND], klB[NCAND];
    float thr[4];
    float redf[5][8];
    int   wcntA[8], wcntB[8];
    int   icntA, icntB;
    float sc[3];
};

__device__ __forceinline__ void warp_kth32(const float* act, const int* cand, float* out2){
    int ln = threadIdx.x & 31;
    unsigned vu[9]; unsigned mxu = 0;
    #pragma unroll
    for (int j = 0; j < 9; j++){
        int idx = ln + j * 32;
        float v = (cand[idx] >= 0) ? act[idx] : -1e9f;
        unsigned u = f2u(v);
        vu[j] = u;
        mxu = max(mxu, u);
    }
    mxu = __reduce_max_sync(0xffffffffu, mxu);
    unsigned T = 0u;
    #pragma unroll
    for (int bit = 31; bit >= 0; bit--){
        unsigned Tc = T | (1u << bit);
        int c = 0;
        #pragma unroll
        for (int j = 0; j < 9; j++) c += (vu[j] >= Tc) ? 1 : 0;
        c = __reduce_add_sync(0xffffffffu, c);
        if (c >= 32) T = Tc;
    }
    if (ln == 0){ out2[0] = u2f(T); out2[1] = u2f(mxu); }
}

__global__ __launch_bounds__(256)
void gate_kernel(const float* __restrict__ qk_pos, const float* __restrict__ v_pos,
                 const float* __restrict__ tau_Q, const float* __restrict__ tau_K,
                 const float* __restrict__ tau_V,
                 const float* __restrict__ qk_neurons, const float* __restrict__ v_neurons,
                 const float* __restrict__ npos_qk, const float* __restrict__ npos_v,
                 const int* __restrict__ cm_qk, const int* __restrict__ cm_v,
                 const float* __restrict__ pos_min, const float* __restrict__ pos_range)
{
    __shared__ GSmem sm;
    int token = blockIdx.x;
    int tid = threadIdx.x;
    int w = tid >> 5, ln = tid & 31;
    float pm0 = pos_min[0], pm1 = pos_min[1];
    float pr0 = pos_range[0], pr1 = pos_range[1];

    float pxA = qk_pos[token*2], pyA = qk_pos[token*2+1];
    float pxB = v_pos[token*2],  pyB = v_pos[token*2+1];
    int cxA = cell_of(pxA, pm0, pr0), cyA = cell_of(pyA, pm1, pr1);
    int cxB = cell_of(pxB, pm0, pr0), cyB = cell_of(pyB, pm1, pr1);

    for (int i = tid; i < NCAND; i += 256){
        int c = i / MPC;
        int rxA = min(max(cxA + c / 3 - 1, 0), GRID_C - 1);
        int ryA = min(max(cyA + c % 3 - 1, 0), GRID_C - 1);
        sm.candA[i] = cm_qk[(rxA * GRID_C + ryA) * MPC + (i & 31)];
        int rxB = min(max(cxB + c / 3 - 1, 0), GRID_C - 1);
        int ryB = min(max(cyB + c % 3 - 1, 0), GRID_C - 1);
        sm.candB[i] = cm_v[(rxB * GRID_C + ryB) * MPC + (i & 31)];
        sm.actA[i] = g_act[0][(size_t)token * NCAND + i];
        sm.actB[i] = g_act[1][(size_t)token * NCAND + i];
    }
    if (tid == 0){ sm.icntA = 0; sm.icntB = 0; }
    __syncthreads();

    if (w == 0)      warp_kth32(sm.actA, sm.candA, &sm.thr[0]);
    else if (w == 1) warp_kth32(sm.actB, sm.candB, &sm.thr[2]);
    __syncthreads();

    float tq = tau_Q[token], tk = tau_K[token], tvt = tau_V[token];
    float akA = sm.thr[0], mxA = sm.thr[1], akB = sm.thr[2], mxB = sm.thr[3];
    float tvQ = egf(akA, tq), tvK = egf(akA, tk), tvV = egf(akB, tvt);
    float stQ = tanhf(egf(mxA, tq)), stK = tanhf(egf(mxA, tk)), stV = tanhf(egf(mxB, tvt));

    float sQ = 0.f, sK = 0.f, sV = 0.f, sQpd = 0.f, sVpd = 0.f;
    for (int r = 0; r < 2; r++){
        int i = r * 256 + tid;
        bool keepA = false, keepB = false;
        float a = 0.f, b = 0.f, wQ = 0.f, wK = 0.f, wV = 0.f;
        int cA = -1, cB = -1;
        if (i < NCAND){
            cA = sm.candA[i];
            a  = sm.actA[i];
            float scA = (cA >= 0) ? a : -1e9f;
            float eQ = egf(scA, tq), eK = egf(scA, tk);
            float kq = (eQ >= tvQ) ? eQ : 0.f;
            float kk = (eK >= tvK) ? eK : 0.f;
            if (cA >= 0){
                wQ = kq; wK = kk;
                sQ += wQ; sK += wK;
                if (wQ > 0.f){
                    float dx = pxA - npos_qk[cA*2], dy = pyA - npos_qk[cA*2+1];
                    sQpd += wQ * (dx*dx + dy*dy);
                }
                keepA = (wQ != 0.f) || (wK != 0.f);
            }
            cB = sm.candB[i];
            b  = sm.actB[i];
            float scB = (cB >= 0) ? b : -1e9f;
            float eV = egf(scB, tvt);
            float kv = (eV >= tvV) ? eV : 0.f;
            if (cB >= 0){
                wV = kv;
                sV += wV;
                if (wV > 0.f){
                    float dx = pxB - npos_v[cB*2], dy = pyB - npos_v[cB*2+1];
                    sVpd += wV * (dx*dx + dy*dy);
                }
                keepB = (wV != 0.f);
            }
        }
        unsigned lt = (1u << ln) - 1u;
        unsigned balA = __ballot_sync(0xffffffffu, keepA);
        unsigned balB = __ballot_sync(0xffffffffu, keepB);
        int pA = __popc(balA & lt), pB = __popc(balB & lt);
        if (ln == 0){ sm.wcntA[w] = __popc(balA); sm.wcntB[w] = __popc(balB); }
        __syncthreads();
        if (tid == 0){
            int bA = sm.icntA, bB = sm.icntB;
            for (int w2 = 0; w2 < 8; w2++){
                int tA = sm.wcntA[w2]; sm.wcntA[w2] = bA; bA += tA;
                int tB = sm.wcntB[w2]; sm.wcntB[w2] = bB; bB += tB;
            }
            sm.icntA = bA; sm.icntB = bB;
        }
        __syncthreads();
        if (keepA){
            int p = sm.wcntA[w] + pA;
            sm.klA[p] = cA; sm.wq[p] = a * wQ; sm.wk[p] = a * wK;
        }
        if (keepB){
            int p = sm.wcntB[w] + pB;
            sm.klB[p] = cB; sm.wv[p] = b * wV;
        }
        __syncthreads();
    }
    #pragma unroll
    for (int o = 16; o; o >>= 1){
        sQ   += __shfl_xor_sync(0xffffffffu, sQ, o);
        sK   += __shfl_xor_sync(0xffffffffu, sK, o);
        sV   += __shfl_xor_sync(0xffffffffu, sV, o);
        sQpd += __shfl_xor_sync(0xffffffffu, sQpd, o);
        sVpd += __shfl_xor_sync(0xffffffffu, sVpd, o);
    }
    if (ln == 0){
        sm.redf[0][w] = sQ; sm.redf[1][w] = sK; sm.redf[2][w] = sV;
        sm.redf[3][w] = sQpd; sm.redf[4][w] = sVpd;
    }
    __syncthreads();
    if (tid == 0){
        float a0=0.f, a1=0.f, a2=0.f, a3=0.f, a4=0.f;
        for (int w2 = 0; w2 < 8; w2++){
            a0 += sm.redf[0][w2]; a1 += sm.redf[1][w2]; a2 += sm.redf[2][w2];
            a3 += sm.redf[3][w2]; a4 += sm.redf[4][w2];
        }
        float scQ = stQ / (a0 + 1e-8f);
        float scK = stK / (a1 + 1e-8f);
        float scV = stV / (a2 + 1e-8f);
        sm.sc[0] = scQ; sm.sc[1] = scK; sm.sc[2] = scV;
        g_posbuf[token] = scQ * a3;
        g_posbuf[NTOK + token] = scV * a4;
    }
    __syncthreads();
    {
        int nkA = sm.icntA;
        float scQ = sm.sc[0], scK = sm.sc[1];
        float2 q = make_float2(0.f, 0.f), k = make_float2(0.f, 0.f);
        #pragma unroll 4
        for (int j = 0; j < nkA; j++){
            const float2* row = (const float2*)(qk_neurons + (size_t)sm.klA[j] * ND);
            float cq = sm.wq[j] * scQ, ck = sm.wk[j] * scK;
            float2 r = row[tid];
            q.x += cq * r.x; q.y += cq * r.y;
            k.x += ck * r.x; k.y += ck * r.y;
        }
        ((float2*)(g_Q + (size_t)token * ND))[tid] = q;
        ((float2*)(g_K + (size_t)token * ND))[tid] = k;
    }
    {
        int nkB = sm.icntB;
        float scV = sm.sc[2];
        float2 v = make_float2(0.f, 0.f);
        #pragma unroll 4
        for (int j = 0; j < nkB; j++){
            const float2* row = (const float2*)(v_neurons + (size_t)sm.klB[j] * ND);
            float cv = sm.wv[j] * scV;
            float2 r = row[tid];
            v.x += cv * r.x; v.y += cv * r.y;
        }
        ((float2*)(g_V + (size_t)token * ND))[tid] = v;
    }
}

// ================= 4-way split-KV causal flash attention =================
__global__ __launch_bounds__(128)
void attn_kernel(){
    __shared__ float QT[64][36];
    __shared__ float Ks[64][68];
    __shared__ float Vs[64][68];
    int tid = threadIdx.x;
    int jj = blockIdx.x & 127;
    int qt = jj >> 2;
    int sp = jj & 3;
    int h  = (blockIdx.x >> 7) & 7;
    int b  = blockIdx.x >> 10;
    int q0 = qt * 32;
    int pb = ((b * NHEAD + h) << 5) | qt;
    int ntile = qt / 2 + 1;
    int kts = sp * ntile / NSPLIT;
    int kte = (sp + 1) * ntile / NSPLIT;

    const float* Qg = g_Q + (size_t)b * NS * ND + h * DHEAD;
    const float* Kg = g_K + (size_t)b * NS * ND + h * DHEAD;
    const float* Vg = g_V + (size_t)b * NS * ND + h * DHEAD;

    int tx = tid & 15, ty = tid >> 4;
    int lane = tid & 31;
    float acc[4][4];
    float m[4], l[4];
    #pragma unroll
    for (int qi = 0; qi < 4; qi++){
        m[qi] = -FLT_MAX; l[qi] = 0.f;
        #pragma unroll
        for (int di = 0; di < 4; di++) acc[qi][di] = 0.f;
    }

    if (kts < kte){
        for (int i = tid; i < 32 * 64; i += 128){
            int r = i >> 6, c = i & 63;
            QT[c][r] = Qg[(size_t)(q0 + r) * ND + c];
        }
        for (int kt = kts; kt < kte; kt++){
            int t0 = kt * 64;
            __syncthreads();
            for (int i = tid; i < 64 * 64; i += 128){
                int r = i >> 6, c = i & 63;
                float kvv = Kg[(size_t)(t0 + r) * ND + c];
                float vvv = Vg[(size_t)(t0 + r) * ND + c];
                Ks[c][r] = kvv;
                Vs[r][c] = vvv;
            }
            __syncthreads();
            float sf[4][4];
            #pragma unroll
            for (int qi = 0; qi < 4; qi++)
                #pragma unroll
                for (int ki = 0; ki < 4; ki++) sf[qi][ki] = 0.f;
            #pragma unroll 4
            for (int d = 0; d < 64; d++){
                float4 qv = *(const float4*)&QT[d][ty * 4];
                float4 kv = *(const float4*)&Ks[d][tx * 4];
                float qa[4] = {qv.x, qv.y, qv.z, qv.w};
                float ka[4] = {kv.x, kv.y, kv.z, kv.w};
                #pragma unroll
                for (int qi = 0; qi < 4; qi++)
                    #pragma unroll
                    for (int ki = 0; ki < 4; ki++) sf[qi][ki] += qa[qi] * ka[ki];
            }
            const float scl = 0.125f;
            bool diag = (t0 + 64 > q0);
            float p[4][4];
            #pragma unroll
            for (int qi = 0; qi < 4; qi++){
                int qg = q0 + ty * 4 + qi;
                float rm = -FLT_MAX;
                #pragma unroll
                for (int ki = 0; ki < 4; ki++){
                    int tg = t0 + tx * 4 + ki;
                    float v = (!diag || tg <= qg) ? sf[qi][ki] * scl : -FLT_MAX;
                    p[qi][ki] = v;
                    rm = fmaxf(rm, v);
                }
                #pragma unroll
                for (int o = 1; o < 16; o <<= 1) rm = fmaxf(rm, __shfl_xor_sync(0xffffffffu, rm, o));
                float mn = fmaxf(m[qi], rm);
                float corr = expf(m[qi] - mn);
                float rs = 0.f;
                #pragma unroll
                for (int ki = 0; ki < 4; ki++){
                    float e = expf(p[qi][ki] - mn);
                    p[qi][ki] = e;
                    rs += e;
                }
                #pragma unroll
                for (int o = 1; o < 16; o <<= 1) rs += __shfl_xor_sync(0xffffffffu, rs, o);
                l[qi] = l[qi] * corr + rs;
                #pragma unroll
                for (int di = 0; di < 4; di++) acc[qi][di] *= corr;
                m[qi] = mn;
            }
            #pragma unroll 2
            for (int tg = 0; tg < 16; tg++){
                int src = (lane & 16) | tg;
                #pragma unroll
                for (int ki = 0; ki < 4; ki++){
                    int t = tg * 4 + ki;
                    float4 vv = *(const float4*)&Vs[t][tx * 4];
                    float pq0 = __shfl_sync(0xffffffffu, p[0][ki], src);
                    float pq1 = __shfl_sync(0xffffffffu, p[1][ki], src);
                    float pq2 = __shfl_sync(0xffffffffu, p[2][ki], src);
                    float pq3 = __shfl_sync(0xffffffffu, p[3][ki], src);
                    acc[0][0] += pq0 * vv.x; acc[0][1] += pq0 * vv.y; acc[0][2] += pq0 * vv.z; acc[0][3] += pq0 * vv.w;
                    acc[1][0] += pq1 * vv.x; acc[1][1] += pq1 * vv.y; acc[1][2] += pq1 * vv.z; acc[1][3] += pq1 * vv.w;
                    acc[2][0] += pq2 * vv.x; acc[2][1] += pq2 * vv.y; acc[2][2] += pq2 * vv.z; acc[2][3] += pq2 * vv.w;
                    acc[3][0] += pq3 * vv.x; acc[3][1] += pq3 * vv.y; acc[3][2] += pq3 * vv.z; acc[3][3] += pq3 * vv.w;
                }
            }
        }
    }
    float* Pa = g_pacc[sp][pb];
    #pragma unroll
    for (int qi = 0; qi < 4; qi++){
        float4 o4;
        o4.x = acc[qi][0]; o4.y = acc[qi][1]; o4.z = acc[qi][2]; o4.w = acc[qi][3];
        *(float4*)&Pa[(ty * 4 + qi) * 64 + tx * 4] = o4;
    }
    if (tx == 0){
        #pragma unroll
        for (int qi = 0; qi < 4; qi++){
            g_pml[sp][pb][ty * 4 + qi] = m[qi];
            g_pml[sp][pb][32 + ty * 4 + qi] = l[qi];
        }
    }
}

// exact 4-way flash-merge of splits -> g_AO
__global__ __launch_bounds__(128)
void attn_merge(){
    int pb = blockIdx.x;
    int qt = pb & 31, h = (pb >> 5) & 7, b = pb >> 8;
    __shared__ float mlc[8][32];
    int tid = threadIdx.x;
    if (tid < 32){
        #pragma unroll
        for (int s = 0; s < NSPLIT; s++){
            mlc[s][tid] = g_pml[s][pb][tid];
            mlc[NSPLIT + s][tid] = g_pml[s][pb][32 + tid];
        }
    }
    __syncthreads();
    float* Og = g_AO + (size_t)b * NS * ND + h * DHEAD;
    for (int i = tid; i < 512; i += 128){
        int r = i >> 4, c4 = i & 15;
        float mm = -FLT_MAX;
        #pragma unroll
        for (int s = 0; s < NSPLIT; s++) mm = fmaxf(mm, mlc[s][r]);
        float cs[NSPLIT]; float den = 0.f;
        #pragma unroll
        for (int s = 0; s < NSPLIT; s++){
            cs[s] = expf(mlc[s][r] - mm);
            den += mlc[NSPLIT + s][r] * cs[s];
        }
        float inv = 1.f / den;
        float4 o = make_float4(0.f, 0.f, 0.f, 0.f);
        #pragma unroll
        for (int s = 0; s < NSPLIT; s++){
            float4 a = *(float4*)&g_pacc[s][pb][r * 64 + c4 * 4];
            o.x += a.x * cs[s]; o.y += a.y * cs[s];
            o.z += a.z * cs[s]; o.w += a.w * cs[s];
        }
        o.x *= inv; o.y *= inv; o.z *= inv; o.w *= inv;
        *(float4*)&Og[(size_t)(qt * 32 + r) * ND + c4 * 4] = o;
    }
}

// ================= final projection: tf32 tensor-core GEMM =================
// out[2048,512] = g_AO @ expand_O. 64x64 block tile, 4 warps of 32x32,
// mma.sync.m16n8k8.tf32 with fp32 accumulation. Block (0,0) also writes pos_loss.
__global__ __launch_bounds__(128)
void out_gemm(const float* __restrict__ Bmat, float* __restrict__ out, int has_tail){
    __shared__ float As[64][20];   // [m][k] pad 20 -> conflict-free frag loads
    __shared__ float Bt[64][17];   // [n][k] pad 17 -> conflict-free fill
    int tid = threadIdx.x;
    if (has_tail && blockIdx.x == 0 && blockIdx.y == 0){
        __shared__ float red[4];
        float s = 0.f;
        for (int i = tid; i < NTOK * 2; i += 128) s += g_posbuf[i];
        #pragma unroll
        for (int o = 16; o; o >>= 1) s += __shfl_xor_sync(0xffffffffu, s, o);
        if ((tid & 31) == 0) red[tid >> 5] = s;
        __syncthreads();
        if (tid == 0){
            float t = red[0] + red[1] + red[2] + red[3];
            out[(size_t)NTOK * ND] = t * (1.0f / (8.0f * 73728.0f));
        }
        __syncthreads();
    }
    int m0 = blockIdx.y * 64, n0 = blockIdx.x * 64;
    int wid = tid >> 5, lane = tid & 31;
    int g = lane >> 2, tig = lane & 3;
    int wm = (wid & 1) * 32, wn = (wid >> 1) * 32;
    float c[2][4][4];
    #pragma unroll
    for (int mi = 0; mi < 2; mi++)
        #pragma unroll
        for (int ni = 0; ni < 4; ni++)
            #pragma unroll
            for (int e = 0; e < 4; e++) c[mi][ni][e] = 0.f;

    for (int k0 = 0; k0 < ND; k0 += 16){
        __syncthreads();
        // A tile 64x16 (float4 loads)
        for (int i = tid; i < 256; i += 128){
            int r = i >> 2, c4 = i & 3;
            float4 v = *(const float4*)&g_AO[(size_t)(m0 + r) * ND + k0 + c4 * 4];
            As[r][c4*4+0] = v.x; As[r][c4*4+1] = v.y;
            As[r][c4*4+2] = v.z; As[r][c4*4+3] = v.w;
        }
        // B tile 16x64 -> transposed [n][k] (scalar stores, stride-17 conflict-free)
        for (int i = tid; i < 1024; i += 128){
            int kk = i >> 6, n = i & 63;
            Bt[n][kk] = Bmat[(size_t)(k0 + kk) * ND + n0 + n];
        }
        __syncthreads();
        #pragma unroll
        for (int kk = 0; kk < 16; kk += 8){
            unsigned a[2][4], bf[4][2];
            #pragma unroll
            for (int mi = 0; mi < 2; mi++){
                int r0 = wm + mi * 16 + g;
                CVT_TF32(a[mi][0], As[r0][kk + tig]);
                CVT_TF32(a[mi][1], As[r0 + 8][kk + tig]);
                CVT_TF32(a[mi][2], As[r0][kk + tig + 4]);
                CVT_TF32(a[mi][3], As[r0 + 8][kk + tig + 4]);
            }
            #pragma unroll
            for (int ni = 0; ni < 4; ni++){
                int nn = wn + ni * 8 + g;
                CVT_TF32(bf[ni][0], Bt[nn][kk + tig]);
                CVT_TF32(bf[ni][1], Bt[nn][kk + tig + 4]);
            }
            #pragma unroll
            for (int mi = 0; mi < 2; mi++)
                #pragma unroll
                for (int ni = 0; ni < 4; ni++){
                    asm volatile(
                        "mma.sync.aligned.m16n8k8.row.col.f32.tf32.tf32.f32 "
                        "{%0,%1,%2,%3},{%4,%5,%6,%7},{%8,%9},{%0,%1,%2,%3};"
                        : "+f"(c[mi][ni][0]), "+f"(c[mi][ni][1]),
                          "+f"(c[mi][ni][2]), "+f"(c[mi][ni][3])
                        : "r"(a[mi][0]), "r"(a[mi][1]), "r"(a[mi][2]), "r"(a[mi][3]),
                          "r"(bf[ni][0]), "r"(bf[ni][1]));
                }
        }
    }
    #pragma unroll
    for (int mi = 0; mi < 2; mi++)
        #pragma unroll
        for (int ni = 0; ni < 4; ni++){
            int r = m0 + wm + mi * 16 + g;
            int cc = n0 + wn + ni * 8 + tig * 2;
            out[(size_t)r * ND + cc]     = c[mi][ni][0];
            out[(size_t)r * ND + cc + 1] = c[mi][ni][1];
            out[(size_t)(r + 8) * ND + cc]     = c[mi][ni][2];
            out[(size_t)(r + 8) * ND + cc + 1] = c[mi][ni][3];
        }
}

extern "C" void kernel_launch(void* const* d_in, const int* in_sizes, int n_in,
                              void* d_out, int out_size){
    const float* x          = (const float*)d_in[0];
    const float* qk_pos     = (const float*)d_in[1];
    const float* v_pos      = (const float*)d_in[2];
    const float* tau_Q      = (const float*)d_in[3];
    const float* tau_K      = (const float*)d_in[4];
    const float* tau_V      = (const float*)d_in[5];
    const float* qk_neurons = (const float*)d_in[6];
    const float* v_neurons  = (const float*)d_in[7];
    const float* npos_qk    = (const float*)d_in[8];
    const float* npos_v     = (const float*)d_in[9];
    const int*   cm_qk      = (const int*)d_in[10];
    const int*   cm_v       = (const int*)d_in[11];
    const float* pos_min    = (const float*)d_in[12];
    const float* pos_range  = (const float*)d_in[13];
    const float* expand_O   = (const float*)d_in[14];
    float* out = (float*)d_out;

    bin_all<<<1, 1024>>>(qk_pos, v_pos, pos_min, pos_range);
    score_kernel<<<1024, 256>>>(x, qk_neurons, v_neurons, cm_qk, cm_v);
    gate_kernel<<<NTOK, 256>>>(qk_pos, v_pos, tau_Q, tau_K, tau_V,
                               qk_neurons, v_neurons, npos_qk, npos_v,
                               cm_qk, cm_v, pos_min, pos_range);
    attn_kernel<<<NB * NHEAD * 32 * NSPLIT, 128>>>();
    attn_merge<<<NPB, 128>>>();
    int has_tail = (out_size > NTOK * ND) ? 1 : 0;
    dim3 g(ND / 64, NTOK / 64);
    out_gemm<<<g, 128>>>(expand_O, out, has_tail);
}